// round 2
// baseline (speedup 1.0000x reference)
#include <cuda_runtime.h>
#include <math.h>

// Problem constants
#define T_SEQ 4096
#define NB    2
#define C_EMB 512
#define NH    8
#define HD    64
#define BT    (NB * T_SEQ)   // 8192

// Scratch (static device globals; no allocation allowed)
__device__ float g_qkv[(size_t)BT * 3 * C_EMB];   // [8192, 1536]
__device__ float g_y[(size_t)BT * C_EMB];         // [8192, 512]

// ---------------------------------------------------------------------------
// Tiled fp32 GEMM: C[M,N] = A[M,K] @ B[K,N], row-major.
// 128x128 block tile, BK=16, 256 threads, 8x8 per thread (split 4+4 fragments
// for conflict-free LDS.128 on both operands).
// Requires M%128==0, N%128==0, K%16==0 (true for all our shapes).
// ---------------------------------------------------------------------------
__global__ __launch_bounds__(256) void gemm128_kernel(
    const float* __restrict__ A, const float* __restrict__ B,
    float* __restrict__ Cmat, int M, int N, int K)
{
    __shared__ float As[16][128];   // k-major: As[k][m]
    __shared__ float Bs[16][128];   // Bs[k][n]

    const int t  = threadIdx.x;
    const int ty = t >> 4;          // 0..15
    const int tx = t & 15;          // 0..15
    const int m0 = blockIdx.y * 128;
    const int n0 = blockIdx.x * 128;

    float acc[8][8];
    #pragma unroll
    for (int i = 0; i < 8; i++)
        #pragma unroll
        for (int j = 0; j < 8; j++) acc[i][j] = 0.f;

    for (int k0 = 0; k0 < K; k0 += 16) {
        // Load A tile (coalesced gmem), store transposed into As[k][m]
        #pragma unroll
        for (int i = 0; i < 2; i++) {
            int idx = t + i * 256;          // 0..511
            int row = idx >> 2;             // 0..127
            int kc  = (idx & 3) * 4;        // 0,4,8,12
            float4 v = *(const float4*)(A + (size_t)(m0 + row) * K + k0 + kc);
            As[kc + 0][row] = v.x;
            As[kc + 1][row] = v.y;
            As[kc + 2][row] = v.z;
            As[kc + 3][row] = v.w;
        }
        // Load B tile (coalesced, direct row-major)
        #pragma unroll
        for (int i = 0; i < 2; i++) {
            int idx = t + i * 256;
            int kr  = idx >> 5;             // 0..15
            int nc  = (idx & 31) * 4;       // 0..124
            *(float4*)(&Bs[kr][nc]) =
                *(const float4*)(B + (size_t)(k0 + kr) * N + n0 + nc);
        }
        __syncthreads();

        #pragma unroll
        for (int k = 0; k < 16; k++) {
            float a[8], bv[8];
            *(float4*)&a[0]  = *(const float4*)(&As[k][ty * 4]);
            *(float4*)&a[4]  = *(const float4*)(&As[k][64 + ty * 4]);
            *(float4*)&bv[0] = *(const float4*)(&Bs[k][tx * 4]);
            *(float4*)&bv[4] = *(const float4*)(&Bs[k][64 + tx * 4]);
            #pragma unroll
            for (int i = 0; i < 8; i++)
                #pragma unroll
                for (int j = 0; j < 8; j++)
                    acc[i][j] = fmaf(a[i], bv[j], acc[i][j]);
        }
        __syncthreads();
    }

    // Store: rows {ty*4+i, 64+ty*4+i}, cols {tx*4+j, 64+tx*4+j}
    #pragma unroll
    for (int i = 0; i < 8; i++) {
        int row = m0 + ((i < 4) ? (ty * 4 + i) : (64 + ty * 4 + (i - 4)));
        float* cp = Cmat + (size_t)row * N + n0;
        *(float4*)(cp + tx * 4)      = make_float4(acc[i][0], acc[i][1], acc[i][2], acc[i][3]);
        *(float4*)(cp + 64 + tx * 4) = make_float4(acc[i][4], acc[i][5], acc[i][6], acc[i][7]);
    }
}

// ---------------------------------------------------------------------------
// Causal flash attention (fp32, online softmax).
// Grid: (T/64, B*H). Block: 256 threads (16x16), each thread owns a 4x4 tile
// of the 64x64 S / O blocks.
// Q and K are stored k-major (d-major) in smem so S=Q@K^T uses the same
// conflict-free LDS.128 pattern as the GEMM; P is stored k-major (c-major)
// for the O+=P@V pass.
// qkv layout per row (b*T+t): [Q(512) | K(512) | V(512)], head h at +h*64.
// ---------------------------------------------------------------------------
#define SST 68   // smem row stride (floats); 68*4B = 272B, 16B-aligned

__global__ __launch_bounds__(256) void attn_kernel(
    const float* __restrict__ qkv, float* __restrict__ y)
{
    extern __shared__ float sm[];
    float* Qst = sm;                 // [64][SST] Qst[d][r] (pre-scaled)
    float* Kst = sm + 64 * SST;      // [64][SST] Kst[d][c]
    float* Vs  = sm + 2 * 64 * SST;  // [64][SST] Vs[c][d]
    float* Pst = sm + 3 * 64 * SST;  // [64][SST] Pst[c][r]

    const int t  = threadIdx.x;
    const int ty = t >> 4;
    const int tx = t & 15;
    const int qt = blockIdx.x;       // query tile (64 rows)
    const int bh = blockIdx.y;
    const int b  = bh >> 3;
    const int h  = bh & 7;
    const float scale = 0.125f;      // 1/sqrt(64)

    const size_t base = (size_t)b * T_SEQ * (3 * C_EMB);
    const float* Qg = qkv + base + (size_t)qt * 64 * (3 * C_EMB) + h * HD;
    const float* Kg = qkv + base + C_EMB + h * HD;
    const float* Vg = qkv + base + 2 * C_EMB + h * HD;

    // Load Q tile transposed into smem, pre-scaled
    #pragma unroll
    for (int i = 0; i < 4; i++) {
        int idx = t + i * 256;           // 0..1023
        int r   = idx >> 4;              // 0..63
        int c4  = (idx & 15) * 4;        // 0..60
        float4 v = *(const float4*)(Qg + (size_t)r * (3 * C_EMB) + c4);
        Qst[(c4 + 0) * SST + r] = v.x * scale;
        Qst[(c4 + 1) * SST + r] = v.y * scale;
        Qst[(c4 + 2) * SST + r] = v.z * scale;
        Qst[(c4 + 3) * SST + r] = v.w * scale;
    }

    float m[4], l[4], o[4][4];
    #pragma unroll
    for (int i = 0; i < 4; i++) {
        m[i] = -1e30f; l[i] = 0.f;
        #pragma unroll
        for (int j = 0; j < 4; j++) o[i][j] = 0.f;
    }

    for (int jt = 0; jt <= qt; jt++) {
        __syncthreads();   // previous iteration's Pst/Vs/Kst reads complete

        // Load K tile (transposed) and V tile (row-major)
        #pragma unroll
        for (int i = 0; i < 4; i++) {
            int idx = t + i * 256;
            int r   = idx >> 4;
            int c4  = (idx & 15) * 4;
            const size_t grow = (size_t)(jt * 64 + r) * (3 * C_EMB);
            float4 kv = *(const float4*)(Kg + grow + c4);
            Kst[(c4 + 0) * SST + r] = kv.x;
            Kst[(c4 + 1) * SST + r] = kv.y;
            Kst[(c4 + 2) * SST + r] = kv.z;
            Kst[(c4 + 3) * SST + r] = kv.w;
            float4 vv = *(const float4*)(Vg + grow + c4);
            *(float4*)(&Vs[r * SST + c4]) = vv;
        }
        __syncthreads();

        // S = (Q*scale) @ K^T  (64x64, 4x4 per thread)
        float s[4][4];
        #pragma unroll
        for (int i = 0; i < 4; i++)
            #pragma unroll
            for (int j = 0; j < 4; j++) s[i][j] = 0.f;

        #pragma unroll 8
        for (int d = 0; d < 64; d++) {
            float a[4], bv[4];
            *(float4*)&a[0]  = *(const float4*)(&Qst[d * SST + ty * 4]);
            *(float4*)&bv[0] = *(const float4*)(&Kst[d * SST + tx * 4]);
            #pragma unroll
            for (int i = 0; i < 4; i++)
                #pragma unroll
                for (int j = 0; j < 4; j++)
                    s[i][j] = fmaf(a[i], bv[j], s[i][j]);
        }

        // Causal mask (only the diagonal tile)
        if (jt == qt) {
            #pragma unroll
            for (int i = 0; i < 4; i++)
                #pragma unroll
                for (int j = 0; j < 4; j++)
                    if (tx * 4 + j > ty * 4 + i) s[i][j] = -1e30f;
        }

        // Online softmax update (row groups = 16 lanes sharing ty)
        #pragma unroll
        for (int i = 0; i < 4; i++) {
            float rowm = fmaxf(fmaxf(s[i][0], s[i][1]), fmaxf(s[i][2], s[i][3]));
            #pragma unroll
            for (int w = 1; w < 16; w <<= 1)
                rowm = fmaxf(rowm, __shfl_xor_sync(0xffffffffu, rowm, w));
            float mnew  = fmaxf(m[i], rowm);
            float alpha = __expf(m[i] - mnew);
            m[i] = mnew;
            float rs = 0.f;
            #pragma unroll
            for (int j = 0; j < 4; j++) {
                s[i][j] = __expf(s[i][j] - mnew);
                rs += s[i][j];
            }
            #pragma unroll
            for (int w = 1; w < 16; w <<= 1)
                rs += __shfl_xor_sync(0xffffffffu, rs, w);
            l[i] = l[i] * alpha + rs;
            #pragma unroll
            for (int j = 0; j < 4; j++) o[i][j] *= alpha;
        }

        // Write P transposed: Pst[c][r]
        #pragma unroll
        for (int i = 0; i < 4; i++)
            #pragma unroll
            for (int j = 0; j < 4; j++)
                Pst[(tx * 4 + j) * SST + (ty * 4 + i)] = s[i][j];
        __syncthreads();

        // O += P @ V
        #pragma unroll 8
        for (int c = 0; c < 64; c++) {
            float a[4], bv[4];
            *(float4*)&a[0]  = *(const float4*)(&Pst[c * SST + ty * 4]);
            *(float4*)&bv[0] = *(const float4*)(&Vs[c * SST + tx * 4]);
            #pragma unroll
            for (int i = 0; i < 4; i++)
                #pragma unroll
                for (int j = 0; j < 4; j++)
                    o[i][j] = fmaf(a[i], bv[j], o[i][j]);
        }
    }

    // Epilogue: normalize and store to y[b, t, h*64 + d]
    float* yg = y + ((size_t)b * T_SEQ + (size_t)qt * 64) * C_EMB + h * HD;
    #pragma unroll
    for (int i = 0; i < 4; i++) {
        float inv = 1.f / l[i];
        float4 v = make_float4(o[i][0] * inv, o[i][1] * inv,
                               o[i][2] * inv, o[i][3] * inv);
        *(float4*)(yg + (size_t)(ty * 4 + i) * C_EMB + tx * 4) = v;
    }
}

// ---------------------------------------------------------------------------
extern "C" void kernel_launch(void* const* d_in, const int* in_sizes, int n_in,
                              void* d_out, int out_size)
{
    const float* x      = (const float*)d_in[0];   // [B,T,C]
    const float* W_attn = (const float*)d_in[1];   // [C, 3C]
    const float* W_proj = (const float*)d_in[2];   // [C, C]
    float* out = (float*)d_out;                    // [B,T,C]

    float* qkv_ptr; float* y_ptr;
    cudaGetSymbolAddress((void**)&qkv_ptr, g_qkv);
    cudaGetSymbolAddress((void**)&y_ptr,  g_y);

    const int smem_attn = 4 * 64 * SST * (int)sizeof(float);  // 69,632 B
    static int attr_set = 0;  // idempotent host-side attribute (not a stream op)
    if (!attr_set) {
        cudaFuncSetAttribute(attn_kernel,
                             cudaFuncAttributeMaxDynamicSharedMemorySize,
                             smem_attn);
        attr_set = 1;
    }

    // 1) qkv = x @ W_attn   (8192 x 1536 x 512)
    gemm128_kernel<<<dim3(3 * C_EMB / 128, BT / 128), 256>>>(
        x, W_attn, qkv_ptr, BT, 3 * C_EMB, C_EMB);

    // 2) causal attention per (q-tile, b*h)
    attn_kernel<<<dim3(T_SEQ / 64, NB * NH), 256, smem_attn>>>(qkv_ptr, y_ptr);

    // 3) out = y @ W_proj   (8192 x 512 x 512)
    gemm128_kernel<<<dim3(C_EMB / 128, BT / 128), 256>>>(
        y_ptr, W_proj, out, BT, C_EMB, C_EMB);
}

// round 3
// speedup vs baseline: 1.1454x; 1.1454x over previous
#include <cuda_runtime.h>
#include <math.h>

// Problem constants
#define T_SEQ 4096
#define NB    2
#define C_EMB 512
#define NH    8
#define HD    64
#define BT    (NB * T_SEQ)   // 8192

// Scratch (static device globals; no allocation allowed)
__device__ float g_qkv[(size_t)BT * 3 * C_EMB];   // [8192, 1536]
__device__ float g_y[(size_t)BT * C_EMB];         // [8192, 512]

// ---------------------------------------------------------------------------
// Tiled fp32 GEMM: C[M,N] = A[M,K] @ B[K,N], row-major. (unchanged from R1)
// 128x128 block tile, BK=16, 256 threads, 8x8 per thread.
// ---------------------------------------------------------------------------
__global__ __launch_bounds__(256) void gemm128_kernel(
    const float* __restrict__ A, const float* __restrict__ B,
    float* __restrict__ Cmat, int M, int N, int K)
{
    __shared__ float As[16][128];   // k-major: As[k][m]
    __shared__ float Bs[16][128];   // Bs[k][n]

    const int t  = threadIdx.x;
    const int ty = t >> 4;          // 0..15
    const int tx = t & 15;          // 0..15
    const int m0 = blockIdx.y * 128;
    const int n0 = blockIdx.x * 128;

    float acc[8][8];
    #pragma unroll
    for (int i = 0; i < 8; i++)
        #pragma unroll
        for (int j = 0; j < 8; j++) acc[i][j] = 0.f;

    for (int k0 = 0; k0 < K; k0 += 16) {
        #pragma unroll
        for (int i = 0; i < 2; i++) {
            int idx = t + i * 256;          // 0..511
            int row = idx >> 2;             // 0..127
            int kc  = (idx & 3) * 4;        // 0,4,8,12
            float4 v = *(const float4*)(A + (size_t)(m0 + row) * K + k0 + kc);
            As[kc + 0][row] = v.x;
            As[kc + 1][row] = v.y;
            As[kc + 2][row] = v.z;
            As[kc + 3][row] = v.w;
        }
        #pragma unroll
        for (int i = 0; i < 2; i++) {
            int idx = t + i * 256;
            int kr  = idx >> 5;             // 0..15
            int nc  = (idx & 31) * 4;       // 0..124
            *(float4*)(&Bs[kr][nc]) =
                *(const float4*)(B + (size_t)(k0 + kr) * N + n0 + nc);
        }
        __syncthreads();

        #pragma unroll
        for (int k = 0; k < 16; k++) {
            float a[8], bv[8];
            *(float4*)&a[0]  = *(const float4*)(&As[k][ty * 4]);
            *(float4*)&a[4]  = *(const float4*)(&As[k][64 + ty * 4]);
            *(float4*)&bv[0] = *(const float4*)(&Bs[k][tx * 4]);
            *(float4*)&bv[4] = *(const float4*)(&Bs[k][64 + tx * 4]);
            #pragma unroll
            for (int i = 0; i < 8; i++)
                #pragma unroll
                for (int j = 0; j < 8; j++)
                    acc[i][j] = fmaf(a[i], bv[j], acc[i][j]);
        }
        __syncthreads();
    }

    #pragma unroll
    for (int i = 0; i < 8; i++) {
        int row = m0 + ((i < 4) ? (ty * 4 + i) : (64 + ty * 4 + (i - 4)));
        float* cp = Cmat + (size_t)row * N + n0;
        *(float4*)(cp + tx * 4)      = make_float4(acc[i][0], acc[i][1], acc[i][2], acc[i][3]);
        *(float4*)(cp + 64 + tx * 4) = make_float4(acc[i][4], acc[i][5], acc[i][6], acc[i][7]);
    }
}

// ---------------------------------------------------------------------------
// Causal flash attention (fp32, online softmax), BM=128 x BN=64 tiles.
// 256 threads (16x16); each thread owns 8 rows x 4 cols of S / O:
// rows {ty*4+i, 64+ty*4+i}, cols {tx*4+j}.  Ratio: 32 FFMA per 12 LDS-floats.
// Heavy q-tiles launch first (qt reversed) for wave balance.
// qkv layout per row (b*T+t): [Q(512) | K(512) | V(512)], head h at +h*64.
// ---------------------------------------------------------------------------
#define SQ 132   // stride for 128-wide rows (Qst, Pst)
#define SK 68    // stride for 64-wide rows (Kst, Vs)

__global__ __launch_bounds__(256, 2) void attn_kernel(
    const float* __restrict__ qkv, float* __restrict__ y)
{
    extern __shared__ float sm[];
    float* Qst = sm;                       // [64][SQ]  Qst[d][r], pre-scaled
    float* Pst = sm + 64 * SQ;             // [64][SQ]  Pst[c][r]
    float* Kst = sm + 2 * 64 * SQ;         // [64][SK]  Kst[d][c]
    float* Vs  = sm + 2 * 64 * SQ + 64*SK; // [64][SK]  Vs[c][d]

    const int t  = threadIdx.x;
    const int ty = t >> 4;
    const int tx = t & 15;
    const int qt = gridDim.x - 1 - blockIdx.x;  // heavy tiles first
    const int bh = blockIdx.y;
    const int b  = bh >> 3;
    const int h  = bh & 7;
    const float scale = 0.125f;            // 1/sqrt(64)

    const size_t base = (size_t)b * T_SEQ * (3 * C_EMB);
    const float* Qg = qkv + base + (size_t)qt * 128 * (3 * C_EMB) + h * HD;
    const float* Kg = qkv + base + C_EMB + h * HD;
    const float* Vg = qkv + base + 2 * C_EMB + h * HD;

    // Load Q tile (128 x 64) transposed into smem, pre-scaled
    #pragma unroll
    for (int i = 0; i < 8; i++) {
        int idx = t + i * 256;             // 0..2047
        int r   = idx >> 4;                // 0..127
        int c4  = (idx & 15) * 4;          // 0..60
        float4 v = *(const float4*)(Qg + (size_t)r * (3 * C_EMB) + c4);
        Qst[(c4 + 0) * SQ + r] = v.x * scale;
        Qst[(c4 + 1) * SQ + r] = v.y * scale;
        Qst[(c4 + 2) * SQ + r] = v.z * scale;
        Qst[(c4 + 3) * SQ + r] = v.w * scale;
    }

    float m[8], l[8], o[8][4];
    #pragma unroll
    for (int i = 0; i < 8; i++) {
        m[i] = -1e30f; l[i] = 0.f;
        #pragma unroll
        for (int j = 0; j < 4; j++) o[i][j] = 0.f;
    }

    const int jt_max = 2 * qt + 1;         // keys jt*64 .. cover rows qt*128+127
    for (int jt = 0; jt <= jt_max; jt++) {
        __syncthreads();   // previous iteration's Kst/Vs/Pst reads complete

        // Load K tile (transposed) and V tile (row-major), 64 x 64 each
        #pragma unroll
        for (int i = 0; i < 4; i++) {
            int idx = t + i * 256;
            int r   = idx >> 4;            // 0..63
            int c4  = (idx & 15) * 4;
            const size_t grow = (size_t)(jt * 64 + r) * (3 * C_EMB);
            float4 kv = *(const float4*)(Kg + grow + c4);
            Kst[(c4 + 0) * SK + r] = kv.x;
            Kst[(c4 + 1) * SK + r] = kv.y;
            Kst[(c4 + 2) * SK + r] = kv.z;
            Kst[(c4 + 3) * SK + r] = kv.w;
            float4 vv = *(const float4*)(Vg + grow + c4);
            *(float4*)(&Vs[r * SK + c4]) = vv;
        }
        __syncthreads();

        // S = (Q*scale) @ K^T   (128x64, 8x4 per thread)
        float s[8][4];
        #pragma unroll
        for (int i = 0; i < 8; i++)
            #pragma unroll
            for (int j = 0; j < 4; j++) s[i][j] = 0.f;

        #pragma unroll 8
        for (int d = 0; d < 64; d++) {
            float a[8], bv[4];
            *(float4*)&a[0]  = *(const float4*)(&Qst[d * SQ + ty * 4]);
            *(float4*)&a[4]  = *(const float4*)(&Qst[d * SQ + 64 + ty * 4]);
            *(float4*)&bv[0] = *(const float4*)(&Kst[d * SK + tx * 4]);
            #pragma unroll
            for (int i = 0; i < 8; i++)
                #pragma unroll
                for (int j = 0; j < 4; j++)
                    s[i][j] = fmaf(a[i], bv[j], s[i][j]);
        }

        // Causal mask — only the top two key tiles can straddle the diagonal
        if (jt >= 2 * qt) {
            #pragma unroll
            for (int i = 0; i < 8; i++) {
                int rloc = (i < 4) ? (ty * 4 + i) : (64 + ty * 4 + (i - 4));
                int rg   = qt * 128 + rloc;
                #pragma unroll
                for (int j = 0; j < 4; j++)
                    if (jt * 64 + tx * 4 + j > rg) s[i][j] = -1e30f;
            }
        }

        // Online softmax update (row groups = 16 lanes sharing ty)
        #pragma unroll
        for (int i = 0; i < 8; i++) {
            float rowm = fmaxf(fmaxf(s[i][0], s[i][1]), fmaxf(s[i][2], s[i][3]));
            #pragma unroll
            for (int w = 1; w < 16; w <<= 1)
                rowm = fmaxf(rowm, __shfl_xor_sync(0xffffffffu, rowm, w));
            float mnew  = fmaxf(m[i], rowm);
            float alpha = __expf(m[i] - mnew);
            m[i] = mnew;
            float rs = 0.f;
            #pragma unroll
            for (int j = 0; j < 4; j++) {
                s[i][j] = __expf(s[i][j] - mnew);
                rs += s[i][j];
            }
            #pragma unroll
            for (int w = 1; w < 16; w <<= 1)
                rs += __shfl_xor_sync(0xffffffffu, rs, w);
            l[i] = l[i] * alpha + rs;
            #pragma unroll
            for (int j = 0; j < 4; j++) o[i][j] *= alpha;
        }

        // Write P transposed: Pst[c][r]
        #pragma unroll
        for (int i = 0; i < 8; i++) {
            int rloc = (i < 4) ? (ty * 4 + i) : (64 + ty * 4 + (i - 4));
            #pragma unroll
            for (int j = 0; j < 4; j++)
                Pst[(tx * 4 + j) * SQ + rloc] = s[i][j];
        }
        __syncthreads();

        // O += P @ V
        #pragma unroll 8
        for (int c = 0; c < 64; c++) {
            float a[8], bv[4];
            *(float4*)&a[0]  = *(const float4*)(&Pst[c * SQ + ty * 4]);
            *(float4*)&a[4]  = *(const float4*)(&Pst[c * SQ + 64 + ty * 4]);
            *(float4*)&bv[0] = *(const float4*)(&Vs[c * SK + tx * 4]);
            #pragma unroll
            for (int i = 0; i < 8; i++)
                #pragma unroll
                for (int j = 0; j < 4; j++)
                    o[i][j] = fmaf(a[i], bv[j], o[i][j]);
        }
    }

    // Epilogue: normalize and store to y[b, t, h*64 + d]
    float* yg = y + ((size_t)b * T_SEQ + (size_t)qt * 128) * C_EMB + h * HD;
    #pragma unroll
    for (int i = 0; i < 8; i++) {
        int rloc = (i < 4) ? (ty * 4 + i) : (64 + ty * 4 + (i - 4));
        float inv = 1.f / l[i];
        float4 v = make_float4(o[i][0] * inv, o[i][1] * inv,
                               o[i][2] * inv, o[i][3] * inv);
        *(float4*)(yg + (size_t)rloc * C_EMB + tx * 4) = v;
    }
}

// ---------------------------------------------------------------------------
extern "C" void kernel_launch(void* const* d_in, const int* in_sizes, int n_in,
                              void* d_out, int out_size)
{
    const float* x      = (const float*)d_in[0];   // [B,T,C]
    const float* W_attn = (const float*)d_in[1];   // [C, 3C]
    const float* W_proj = (const float*)d_in[2];   // [C, C]
    float* out = (float*)d_out;                    // [B,T,C]

    float* qkv_ptr; float* y_ptr;
    cudaGetSymbolAddress((void**)&qkv_ptr, g_qkv);
    cudaGetSymbolAddress((void**)&y_ptr,  g_y);

    const int smem_attn = (2 * 64 * SQ + 2 * 64 * SK) * (int)sizeof(float); // 102,400 B
    static int attr_set = 0;
    if (!attr_set) {
        cudaFuncSetAttribute(attn_kernel,
                             cudaFuncAttributeMaxDynamicSharedMemorySize,
                             smem_attn);
        attr_set = 1;
    }

    // 1) qkv = x @ W_attn   (8192 x 1536 x 512)
    gemm128_kernel<<<dim3(3 * C_EMB / 128, BT / 128), 256>>>(
        x, W_attn, qkv_ptr, BT, 3 * C_EMB, C_EMB);

    // 2) causal attention per (q-tile, b*h): 128-row q tiles
    attn_kernel<<<dim3(T_SEQ / 128, NB * NH), 256, smem_attn>>>(qkv_ptr, y_ptr);

    // 3) out = y @ W_proj   (8192 x 512 x 512)
    gemm128_kernel<<<dim3(C_EMB / 128, BT / 128), 256>>>(
        y_ptr, W_proj, out, BT, C_EMB, C_EMB);
}

// round 6
// speedup vs baseline: 1.2508x; 1.0919x over previous
#include <cuda_runtime.h>
#include <cuda_bf16.h>
#include <cstdint>
#include <math.h>

// Problem constants
#define T_SEQ 4096
#define NB    2
#define C_EMB 512
#define NH    8
#define HD    64
#define BT    (NB * T_SEQ)   // 8192

// Scratch (static device globals; no allocation allowed)
__device__ float g_qkv[(size_t)BT * 3 * C_EMB];              // [8192, 1536]
__device__ float g_y[(size_t)BT * C_EMB];                    // [8192, 512]
__device__ __nv_bfloat16 g_xhi[(size_t)BT * C_EMB];          // x or y hi  [8192,512]
__device__ __nv_bfloat16 g_xlo[(size_t)BT * C_EMB];          // x or y lo
__device__ __nv_bfloat16 g_wa_hi[(size_t)3 * C_EMB * C_EMB]; // W_attn^T hi [1536,512]
__device__ __nv_bfloat16 g_wa_lo[(size_t)3 * C_EMB * C_EMB];
__device__ __nv_bfloat16 g_wp_hi[(size_t)C_EMB * C_EMB];     // W_proj^T hi [512,512]
__device__ __nv_bfloat16 g_wp_lo[(size_t)C_EMB * C_EMB];

// ============================================================================
// mma.sync helpers (sm_80+ PTX — works on plain sm_103 target)
// ============================================================================
__device__ __forceinline__ uint32_t smem_u32(const void* p) {
    uint32_t a;
    asm("{ .reg .u64 t; cvta.to.shared.u64 t, %1; cvt.u32.u64 %0, t; }"
        : "=r"(a) : "l"(p));
    return a;
}
__device__ __forceinline__ void ldm_x4(uint32_t addr, uint32_t& r0, uint32_t& r1,
                                       uint32_t& r2, uint32_t& r3) {
    asm volatile("ldmatrix.sync.aligned.m8n8.x4.shared.b16 {%0,%1,%2,%3}, [%4];"
                 : "=r"(r0), "=r"(r1), "=r"(r2), "=r"(r3) : "r"(addr));
}
__device__ __forceinline__ void mma_bf16(float* d, const uint32_t* a,
                                         uint32_t b0, uint32_t b1) {
    asm volatile(
        "mma.sync.aligned.m16n8k16.row.col.f32.bf16.bf16.f32 "
        "{%0,%1,%2,%3}, {%4,%5,%6,%7}, {%8,%9}, {%0,%1,%2,%3};"
        : "+f"(d[0]), "+f"(d[1]), "+f"(d[2]), "+f"(d[3])
        : "r"(a[0]), "r"(a[1]), "r"(a[2]), "r"(a[3]), "r"(b0), "r"(b1));
}

// ============================================================================
// Fast exp on fma/alu pipes (no MUFU). Valid for x <= 0; ~2e-6 rel err.
// ============================================================================
__device__ __forceinline__ float fexp(float x) {
    float y = fmaxf(x * 1.44269504088896341f, -126.0f);
    float t = y + 12582912.0f;                    // 1.5*2^23 round trick
    int   n = __float_as_int(t) - 0x4B400000;
    float f = y - (t - 12582912.0f);              // f in [-0.5, 0.5]
    float p = fmaf(f, 0.0013333558f, 0.0096181291f);
    p = fmaf(f, p, 0.0555041087f);
    p = fmaf(f, p, 0.2402264791f);
    p = fmaf(f, p, 0.6931472028f);
    p = fmaf(f, p, 1.0f);
    return __int_as_float(__float_as_int(p) + (n << 23));
}

// ============================================================================
// Prep kernels: fp32 -> bf16 hi/lo split
// ============================================================================
__global__ __launch_bounds__(256) void convert_split(
    const float* __restrict__ src, __nv_bfloat16* __restrict__ hi,
    __nv_bfloat16* __restrict__ lo, int n4)
{
    int i = blockIdx.x * 256 + threadIdx.x;
    if (i >= n4) return;
    float4 v = ((const float4*)src)[i];
    __nv_bfloat16 h0 = __float2bfloat16(v.x), h1 = __float2bfloat16(v.y);
    __nv_bfloat16 h2 = __float2bfloat16(v.z), h3 = __float2bfloat16(v.w);
    __nv_bfloat16 l0 = __float2bfloat16(v.x - __bfloat162float(h0));
    __nv_bfloat16 l1 = __float2bfloat16(v.y - __bfloat162float(h1));
    __nv_bfloat16 l2 = __float2bfloat16(v.z - __bfloat162float(h2));
    __nv_bfloat16 l3 = __float2bfloat16(v.w - __bfloat162float(h3));
    ((__nv_bfloat162*)hi)[i * 2 + 0] = __nv_bfloat162(h0, h1);
    ((__nv_bfloat162*)hi)[i * 2 + 1] = __nv_bfloat162(h2, h3);
    ((__nv_bfloat162*)lo)[i * 2 + 0] = __nv_bfloat162(l0, l1);
    ((__nv_bfloat162*)lo)[i * 2 + 1] = __nv_bfloat162(l2, l3);
}

// W [K,N] row-major -> Wt hi/lo [N,K] (K-major) bf16 split. grid (N/32, K/32).
__global__ __launch_bounds__(256) void convert_wT(
    const float* __restrict__ W, __nv_bfloat16* __restrict__ Thi,
    __nv_bfloat16* __restrict__ Tlo, int K, int N)
{
    __shared__ float tile[32][33];
    const int bx = blockIdx.x * 32, by = blockIdx.y * 32;
    const int tx = threadIdx.x & 31, ty = threadIdx.x >> 5;   // ty 0..7
    #pragma unroll
    for (int i = 0; i < 4; i++) {
        int r = ty + i * 8;
        tile[r][tx] = W[(size_t)(by + r) * N + bx + tx];
    }
    __syncthreads();
    #pragma unroll
    for (int i = 0; i < 4; i++) {
        int r = ty + i * 8;                       // output row n = bx + r
        float v = tile[tx][r];                    // = W[by+tx][bx+r]
        __nv_bfloat16 h = __float2bfloat16(v);
        __nv_bfloat16 l = __float2bfloat16(v - __bfloat162float(h));
        size_t o = (size_t)(bx + r) * K + by + tx;
        Thi[o] = h; Tlo[o] = l;
    }
}

// ============================================================================
// mma.sync bf16-split GEMM: C[M,N] = A[M,512] @ B[N,512]^T.
// A, B given as K-major bf16 hi/lo. 3-term: hi*hi + hi*lo + lo*hi.
// Block 128x128, BK=32, 256 threads = 8 warps (2 m x 4 n), warp tile 64x32
// (4 x 4 m16n8k16 tiles). Smem stride 40 halves -> conflict-free ldmatrix.
// ============================================================================
#define GK_TOT 512
#define GBK    32
#define SROW   40   // halves per smem row (80 B)

__global__ __launch_bounds__(256) void mma_gemm(
    const __nv_bfloat16* __restrict__ Ahi, const __nv_bfloat16* __restrict__ Alo,
    const __nv_bfloat16* __restrict__ Bhi, const __nv_bfloat16* __restrict__ Blo,
    float* __restrict__ C, int M, int N)
{
    extern __shared__ char smem[];
    const uint32_t sb = smem_u32(smem);
    const int TILE_B = 128 * SROW * 2;           // 10240 bytes per tile
    const uint32_t sAhi = sb;
    const uint32_t sAlo = sb + TILE_B;
    const uint32_t sBhi = sb + 2 * TILE_B;
    const uint32_t sBlo = sb + 3 * TILE_B;

    const int t    = threadIdx.x;
    const int wid  = t >> 5;
    const int lane = t & 31;
    const int m0   = blockIdx.y * 128;
    const int n0   = blockIdx.x * 128;
    const int wm0  = (wid & 1) * 64;             // warp m offset (0/64)
    const int wn0  = (wid >> 1) * 32;            // warp n offset (0/32/64/96)

    float acc[4][4][4];
    #pragma unroll
    for (int i = 0; i < 4; i++)
        #pragma unroll
        for (int j = 0; j < 4; j++)
            #pragma unroll
            for (int k = 0; k < 4; k++) acc[i][j][k] = 0.f;

    // ldmatrix lane addresses (byte offsets within a tile)
    const uint32_t aoff = ((uint32_t)(lane & 15) * SROW + (lane >> 4) * 8) * 2;
    const uint32_t boff = ((uint32_t)(((lane >> 4) & 1) * 8 + (lane & 7)) * SROW
                          + ((lane >> 3) & 1) * 8) * 2;

    for (int ch = 0; ch < GK_TOT / GBK; ch++) {
        // ---- stage 4 tiles: 128 rows x 32 halves each ----
        #pragma unroll
        for (int i = 0; i < 2; i++) {
            int u = t + i * 256;                  // 0..511
            int r = u >> 2;                       // 0..127
            int c = (u & 3) * 8;                  // halves: 0,8,16,24
            uint32_t so = (uint32_t)(r * SROW + c) * 2;
            size_t ga = (size_t)(m0 + r) * GK_TOT + ch * GBK + c;
            *(uint4*)(smem + (sAhi - sb) + so) = *(const uint4*)(Ahi + ga);
            *(uint4*)(smem + (sAlo - sb) + so) = *(const uint4*)(Alo + ga);
            size_t gb = (size_t)(n0 + r) * GK_TOT + ch * GBK + c;
            *(uint4*)(smem + (sBhi - sb) + so) = *(const uint4*)(Bhi + gb);
            *(uint4*)(smem + (sBlo - sb) + so) = *(const uint4*)(Blo + gb);
        }
        __syncthreads();

        #pragma unroll
        for (int ks = 0; ks < 2; ks++) {
            const uint32_t kb = ks * 16 * 2;      // k-step byte offset
            uint32_t ah[4][4], al[4][4], bh[2][4], bl[2][4];
            #pragma unroll
            for (int mt = 0; mt < 4; mt++) {
                uint32_t ra = (uint32_t)((wm0 + mt * 16) * SROW) * 2 + aoff + kb;
                ldm_x4(sAhi + ra, ah[mt][0], ah[mt][1], ah[mt][2], ah[mt][3]);
                ldm_x4(sAlo + ra, al[mt][0], al[mt][1], al[mt][2], al[mt][3]);
            }
            #pragma unroll
            for (int np = 0; np < 2; np++) {
                uint32_t rb = (uint32_t)((wn0 + np * 16) * SROW) * 2 + boff + kb;
                ldm_x4(sBhi + rb, bh[np][0], bh[np][1], bh[np][2], bh[np][3]);
                ldm_x4(sBlo + rb, bl[np][0], bl[np][1], bl[np][2], bl[np][3]);
            }
            #pragma unroll
            for (int mt = 0; mt < 4; mt++)
                #pragma unroll
                for (int nt = 0; nt < 4; nt++) {
                    uint32_t h0 = bh[nt >> 1][(nt & 1) * 2];
                    uint32_t h1 = bh[nt >> 1][(nt & 1) * 2 + 1];
                    uint32_t l0 = bl[nt >> 1][(nt & 1) * 2];
                    uint32_t l1 = bl[nt >> 1][(nt & 1) * 2 + 1];
                    mma_bf16(acc[mt][nt], ah[mt], h0, h1);   // hi*hi
                    mma_bf16(acc[mt][nt], ah[mt], l0, l1);   // hi*lo
                    mma_bf16(acc[mt][nt], al[mt], h0, h1);   // lo*hi
                }
        }
        __syncthreads();
    }

    // ---- epilogue: standard m16n8 fragment layout -> gmem float2 stores ----
    const int g  = lane >> 2;
    const int cq = (lane & 3) * 2;
    #pragma unroll
    for (int mt = 0; mt < 4; mt++)
        #pragma unroll
        for (int nt = 0; nt < 4; nt++) {
            float* cp = C + (size_t)(m0 + wm0 + mt * 16 + g) * N
                          + n0 + wn0 + nt * 8 + cq;
            *(float2*)cp = make_float2(acc[mt][nt][0], acc[mt][nt][1]);
            *(float2*)(cp + (size_t)8 * N) = make_float2(acc[mt][nt][2], acc[mt][nt][3]);
        }
}

// ============================================================================
// Causal flash attention (fp32 FFMA, online softmax, poly-exp), BM=128 x BN=64.
// ============================================================================
#define SQ 132
#define SK 68

__global__ __launch_bounds__(256, 2) void attn_kernel(
    const float* __restrict__ qkv, float* __restrict__ y)
{
    extern __shared__ float sm[];
    float* Qst = sm;                         // [64][SQ]  Qst[d][r], pre-scaled
    float* Pst = sm + 64 * SQ;               // [64][SQ]  Pst[c][r]
    float* Kst = sm + 2 * 64 * SQ;           // [64][SK]  Kst[d][c]
    float* Vs  = sm + 2 * 64 * SQ + 64 * SK; // [64][SK]  Vs[c][d]

    const int t  = threadIdx.x;
    const int ty = t >> 4;
    const int tx = t & 15;
    const int qt = gridDim.x - 1 - blockIdx.x;
    const int bh = blockIdx.y;
    const int b  = bh >> 3;
    const int h  = bh & 7;
    const float scale = 0.125f;

    const size_t base = (size_t)b * T_SEQ * (3 * C_EMB);
    const float* Qg = qkv + base + (size_t)qt * 128 * (3 * C_EMB) + h * HD;
    const float* Kg = qkv + base + C_EMB + h * HD;
    const float* Vg = qkv + base + 2 * C_EMB + h * HD;

    #pragma unroll
    for (int i = 0; i < 8; i++) {
        int idx = t + i * 256;
        int r   = idx >> 4;
        int c4  = (idx & 15) * 4;
        float4 v = *(const float4*)(Qg + (size_t)r * (3 * C_EMB) + c4);
        Qst[(c4 + 0) * SQ + r] = v.x * scale;
        Qst[(c4 + 1) * SQ + r] = v.y * scale;
        Qst[(c4 + 2) * SQ + r] = v.z * scale;
        Qst[(c4 + 3) * SQ + r] = v.w * scale;
    }

    float m[8], l[8], o[8][4];
    #pragma unroll
    for (int i = 0; i < 8; i++) {
        m[i] = -1e30f; l[i] = 0.f;
        #pragma unroll
        for (int j = 0; j < 4; j++) o[i][j] = 0.f;
    }

    const int jt_max = 2 * qt + 1;
    for (int jt = 0; jt <= jt_max; jt++) {
        __syncthreads();
        #pragma unroll
        for (int i = 0; i < 4; i++) {
            int idx = t + i * 256;
            int r   = idx >> 4;
            int c4  = (idx & 15) * 4;
            const size_t grow = (size_t)(jt * 64 + r) * (3 * C_EMB);
            float4 kv = *(const float4*)(Kg + grow + c4);
            Kst[(c4 + 0) * SK + r] = kv.x;
            Kst[(c4 + 1) * SK + r] = kv.y;
            Kst[(c4 + 2) * SK + r] = kv.z;
            Kst[(c4 + 3) * SK + r] = kv.w;
            float4 vv = *(const float4*)(Vg + grow + c4);
            *(float4*)(&Vs[r * SK + c4]) = vv;
        }
        __syncthreads();

        float s[8][4];
        #pragma unroll
        for (int i = 0; i < 8; i++)
            #pragma unroll
            for (int j = 0; j < 4; j++) s[i][j] = 0.f;

        #pragma unroll 8
        for (int d = 0; d < 64; d++) {
            float a[8], bv[4];
            *(float4*)&a[0]  = *(const float4*)(&Qst[d * SQ + ty * 4]);
            *(float4*)&a[4]  = *(const float4*)(&Qst[d * SQ + 64 + ty * 4]);
            *(float4*)&bv[0] = *(const float4*)(&Kst[d * SK + tx * 4]);
            #pragma unroll
            for (int i = 0; i < 8; i++)
                #pragma unroll
                for (int j = 0; j < 4; j++)
                    s[i][j] = fmaf(a[i], bv[j], s[i][j]);
        }

        if (jt >= 2 * qt) {
            #pragma unroll
            for (int i = 0; i < 8; i++) {
                int rloc = (i < 4) ? (ty * 4 + i) : (64 + ty * 4 + (i - 4));
                int rg   = qt * 128 + rloc;
                #pragma unroll
                for (int j = 0; j < 4; j++)
                    if (jt * 64 + tx * 4 + j > rg) s[i][j] = -1e30f;
            }
        }

        #pragma unroll
        for (int i = 0; i < 8; i++) {
            float rowm = fmaxf(fmaxf(s[i][0], s[i][1]), fmaxf(s[i][2], s[i][3]));
            #pragma unroll
            for (int w = 1; w < 16; w <<= 1)
                rowm = fmaxf(rowm, __shfl_xor_sync(0xffffffffu, rowm, w));
            float mnew  = fmaxf(m[i], rowm);
            float alpha = fexp(m[i] - mnew);
            m[i] = mnew;
            float rs = 0.f;
            #pragma unroll
            for (int j = 0; j < 4; j++) {
                s[i][j] = fexp(s[i][j] - mnew);
                rs += s[i][j];
            }
            #pragma unroll
            for (int w = 1; w < 16; w <<= 1)
                rs += __shfl_xor_sync(0xffffffffu, rs, w);
            l[i] = l[i] * alpha + rs;
            #pragma unroll
            for (int j = 0; j < 4; j++) o[i][j] *= alpha;
        }

        #pragma unroll
        for (int i = 0; i < 8; i++) {
            int rloc = (i < 4) ? (ty * 4 + i) : (64 + ty * 4 + (i - 4));
            #pragma unroll
            for (int j = 0; j < 4; j++)
                Pst[(tx * 4 + j) * SQ + rloc] = s[i][j];
        }
        __syncthreads();

        #pragma unroll 8
        for (int c = 0; c < 64; c++) {
            float a[8], bv[4];
            *(float4*)&a[0]  = *(const float4*)(&Pst[c * SQ + ty * 4]);
            *(float4*)&a[4]  = *(const float4*)(&Pst[c * SQ + 64 + ty * 4]);
            *(float4*)&bv[0] = *(const float4*)(&Vs[c * SK + tx * 4]);
            #pragma unroll
            for (int i = 0; i < 8; i++)
                #pragma unroll
                for (int j = 0; j < 4; j++)
                    o[i][j] = fmaf(a[i], bv[j], o[i][j]);
        }
    }

    float* yg = y + ((size_t)b * T_SEQ + (size_t)qt * 128) * C_EMB + h * HD;
    #pragma unroll
    for (int i = 0; i < 8; i++) {
        int rloc = (i < 4) ? (ty * 4 + i) : (64 + ty * 4 + (i - 4));
        float inv = 1.f / l[i];
        float4 v = make_float4(o[i][0] * inv, o[i][1] * inv,
                               o[i][2] * inv, o[i][3] * inv);
        *(float4*)(yg + (size_t)rloc * C_EMB + tx * 4) = v;
    }
}

// ============================================================================
extern "C" void kernel_launch(void* const* d_in, const int* in_sizes, int n_in,
                              void* d_out, int out_size)
{
    const float* x      = (const float*)d_in[0];   // [B,T,C]
    const float* W_attn = (const float*)d_in[1];   // [C, 3C]
    const float* W_proj = (const float*)d_in[2];   // [C, C]
    float* out = (float*)d_out;                    // [B,T,C]

    float *qkv_ptr, *y_ptr;
    __nv_bfloat16 *xhi, *xlo, *wahi, *walo, *wphi, *wplo;
    cudaGetSymbolAddress((void**)&qkv_ptr, g_qkv);
    cudaGetSymbolAddress((void**)&y_ptr,  g_y);
    cudaGetSymbolAddress((void**)&xhi, g_xhi);
    cudaGetSymbolAddress((void**)&xlo, g_xlo);
    cudaGetSymbolAddress((void**)&wahi, g_wa_hi);
    cudaGetSymbolAddress((void**)&walo, g_wa_lo);
    cudaGetSymbolAddress((void**)&wphi, g_wp_hi);
    cudaGetSymbolAddress((void**)&wplo, g_wp_lo);

    const int smem_attn = (2 * 64 * SQ + 2 * 64 * SK) * (int)sizeof(float); // 102,400
    const int smem_gemm = 4 * 128 * SROW * 2;                               // 40,960
    static int attr_set = 0;
    if (!attr_set) {
        cudaFuncSetAttribute(attn_kernel,
                             cudaFuncAttributeMaxDynamicSharedMemorySize, smem_attn);
        cudaFuncSetAttribute(mma_gemm,
                             cudaFuncAttributeMaxDynamicSharedMemorySize, smem_gemm);
        attr_set = 1;
    }

    // Prep: weights transposed+split (K-major), x split
    convert_wT<<<dim3(3 * C_EMB / 32, C_EMB / 32), 256>>>(W_attn, wahi, walo, C_EMB, 3 * C_EMB);
    convert_wT<<<dim3(C_EMB / 32, C_EMB / 32), 256>>>(W_proj, wphi, wplo, C_EMB, C_EMB);
    convert_split<<<(BT * C_EMB / 4 + 255) / 256, 256>>>(x, xhi, xlo, BT * C_EMB / 4);

    // 1) qkv = x @ W_attn  (mma.sync bf16 split)
    mma_gemm<<<dim3(3 * C_EMB / 128, BT / 128), 256, smem_gemm>>>(
        xhi, xlo, wahi, walo, qkv_ptr, BT, 3 * C_EMB);

    // 2) causal attention
    attn_kernel<<<dim3(T_SEQ / 128, NB * NH), 256, smem_attn>>>(qkv_ptr, y_ptr);

    // 3) out = y @ W_proj  (mma.sync); reuse xhi/xlo for y split
    convert_split<<<(BT * C_EMB / 4 + 255) / 256, 256>>>(y_ptr, xhi, xlo, BT * C_EMB / 4);
    mma_gemm<<<dim3(C_EMB / 128, BT / 128), 256, smem_gemm>>>(
        xhi, xlo, wphi, wplo, out, BT, C_EMB);
}

// round 8
// speedup vs baseline: 2.8141x; 2.2499x over previous
#include <cuda_runtime.h>
#include <cuda_bf16.h>
#include <cstdint>
#include <math.h>

// Problem constants
#define T_SEQ 4096
#define NB    2
#define C_EMB 512
#define NH    8
#define HD    64
#define BT    (NB * T_SEQ)   // 8192

// Scratch (static device globals; no allocation allowed)
__device__ float g_qkv[(size_t)BT * 3 * C_EMB];              // [8192, 1536]
__device__ float g_y[(size_t)BT * C_EMB];                    // [8192, 512]
__device__ __nv_bfloat16 g_xhi[(size_t)BT * C_EMB];          // x or y hi  [8192,512]
__device__ __nv_bfloat16 g_xlo[(size_t)BT * C_EMB];          // x or y lo
__device__ __nv_bfloat16 g_wa_hi[(size_t)3 * C_EMB * C_EMB]; // W_attn^T hi [1536,512]
__device__ __nv_bfloat16 g_wa_lo[(size_t)3 * C_EMB * C_EMB];
__device__ __nv_bfloat16 g_wp_hi[(size_t)C_EMB * C_EMB];     // W_proj^T hi [512,512]
__device__ __nv_bfloat16 g_wp_lo[(size_t)C_EMB * C_EMB];

// ============================================================================
// mma.sync helpers (sm_80+ PTX — works on plain sm_103 target)
// ============================================================================
__device__ __forceinline__ uint32_t smem_u32(const void* p) {
    uint32_t a;
    asm("{ .reg .u64 t; cvta.to.shared.u64 t, %1; cvt.u32.u64 %0, t; }"
        : "=r"(a) : "l"(p));
    return a;
}
__device__ __forceinline__ void ldm_x4(uint32_t addr, uint32_t& r0, uint32_t& r1,
                                       uint32_t& r2, uint32_t& r3) {
    asm volatile("ldmatrix.sync.aligned.m8n8.x4.shared.b16 {%0,%1,%2,%3}, [%4];"
                 : "=r"(r0), "=r"(r1), "=r"(r2), "=r"(r3) : "r"(addr));
}
__device__ __forceinline__ void ldm_x4t(uint32_t addr, uint32_t& r0, uint32_t& r1,
                                        uint32_t& r2, uint32_t& r3) {
    asm volatile("ldmatrix.sync.aligned.m8n8.x4.trans.shared.b16 {%0,%1,%2,%3}, [%4];"
                 : "=r"(r0), "=r"(r1), "=r"(r2), "=r"(r3) : "r"(addr));
}
__device__ __forceinline__ void mma_bf16(float* d, const uint32_t* a,
                                         uint32_t b0, uint32_t b1) {
    asm volatile(
        "mma.sync.aligned.m16n8k16.row.col.f32.bf16.bf16.f32 "
        "{%0,%1,%2,%3}, {%4,%5,%6,%7}, {%8,%9}, {%0,%1,%2,%3};"
        : "+f"(d[0]), "+f"(d[1]), "+f"(d[2]), "+f"(d[3])
        : "r"(a[0]), "r"(a[1]), "r"(a[2]), "r"(a[3]), "r"(b0), "r"(b1));
}
// pack two floats to bf16x2: lo half = a, hi half = b
__device__ __forceinline__ uint32_t pack_bf16(float a, float b) {
    uint32_t r;
    asm("cvt.rn.bf16x2.f32 %0, %1, %2;" : "=r"(r) : "f"(b), "f"(a));
    return r;
}
// hi/lo split of a float pair into two bf16x2 regs
__device__ __forceinline__ void split2(float x, float y, uint32_t& h, uint32_t& l) {
    h = pack_bf16(x, y);
    float xh = __uint_as_float((h & 0xFFFFu) << 16);
    float yh = __uint_as_float(h & 0xFFFF0000u);
    l = pack_bf16(x - xh, y - yh);
}

// ============================================================================
// Fast exp on fma/alu pipes (no MUFU). Valid for x <= 0; ~2e-6 rel err.
// ============================================================================
__device__ __forceinline__ float fexp(float x) {
    float y = fmaxf(x * 1.44269504088896341f, -126.0f);
    float t = y + 12582912.0f;                    // 1.5*2^23 round trick
    int   n = __float_as_int(t) - 0x4B400000;
    float f = y - (t - 12582912.0f);              // f in [-0.5, 0.5]
    float p = fmaf(f, 0.0013333558f, 0.0096181291f);
    p = fmaf(f, p, 0.0555041087f);
    p = fmaf(f, p, 0.2402264791f);
    p = fmaf(f, p, 0.6931472028f);
    p = fmaf(f, p, 1.0f);
    return __int_as_float(__float_as_int(p) + (n << 23));
}

// ============================================================================
// Prep kernels: fp32 -> bf16 hi/lo split
// ============================================================================
__global__ __launch_bounds__(256) void convert_split(
    const float* __restrict__ src, __nv_bfloat16* __restrict__ hi,
    __nv_bfloat16* __restrict__ lo, int n4)
{
    int i = blockIdx.x * 256 + threadIdx.x;
    if (i >= n4) return;
    float4 v = ((const float4*)src)[i];
    uint32_t h0, l0, h1, l1;
    split2(v.x, v.y, h0, l0);
    split2(v.z, v.w, h1, l1);
    ((uint2*)hi)[i] = make_uint2(h0, h1);
    ((uint2*)lo)[i] = make_uint2(l0, l1);
}

// W [K,N] row-major -> Wt hi/lo [N,K] (K-major) bf16 split. grid (N/32, K/32).
__global__ __launch_bounds__(256) void convert_wT(
    const float* __restrict__ W, __nv_bfloat16* __restrict__ Thi,
    __nv_bfloat16* __restrict__ Tlo, int K, int N)
{
    __shared__ float tile[32][33];
    const int bx = blockIdx.x * 32, by = blockIdx.y * 32;
    const int tx = threadIdx.x & 31, ty = threadIdx.x >> 5;   // ty 0..7
    #pragma unroll
    for (int i = 0; i < 4; i++) {
        int r = ty + i * 8;
        tile[r][tx] = W[(size_t)(by + r) * N + bx + tx];
    }
    __syncthreads();
    #pragma unroll
    for (int i = 0; i < 4; i++) {
        int r = ty + i * 8;                       // output row n = bx + r
        float v = tile[tx][r];                    // = W[by+tx][bx+r]
        __nv_bfloat16 h = __float2bfloat16(v);
        __nv_bfloat16 l = __float2bfloat16(v - __bfloat162float(h));
        size_t o = (size_t)(bx + r) * K + by + tx;
        Thi[o] = h; Tlo[o] = l;
    }
}

// ============================================================================
// mma.sync bf16-split GEMM: C[M,N] = A[M,512] @ B[N,512]^T.  (as R5)
// ============================================================================
#define GK_TOT 512
#define GBK    32
#define SROW   40   // halves per smem row (80 B)

__global__ __launch_bounds__(256) void mma_gemm(
    const __nv_bfloat16* __restrict__ Ahi, const __nv_bfloat16* __restrict__ Alo,
    const __nv_bfloat16* __restrict__ Bhi, const __nv_bfloat16* __restrict__ Blo,
    float* __restrict__ C, int M, int N)
{
    extern __shared__ char smem[];
    const uint32_t sb = smem_u32(smem);
    const int TILE_B = 128 * SROW * 2;           // 10240 bytes per tile
    const uint32_t sAhi = sb;
    const uint32_t sAlo = sb + TILE_B;
    const uint32_t sBhi = sb + 2 * TILE_B;
    const uint32_t sBlo = sb + 3 * TILE_B;

    const int t    = threadIdx.x;
    const int wid  = t >> 5;
    const int lane = t & 31;
    const int m0   = blockIdx.y * 128;
    const int n0   = blockIdx.x * 128;
    const int wm0  = (wid & 1) * 64;
    const int wn0  = (wid >> 1) * 32;

    float acc[4][4][4];
    #pragma unroll
    for (int i = 0; i < 4; i++)
        #pragma unroll
        for (int j = 0; j < 4; j++)
            #pragma unroll
            for (int k = 0; k < 4; k++) acc[i][j][k] = 0.f;

    const uint32_t aoff = ((uint32_t)(lane & 15) * SROW + (lane >> 4) * 8) * 2;
    const uint32_t boff = ((uint32_t)(((lane >> 4) & 1) * 8 + (lane & 7)) * SROW
                          + ((lane >> 3) & 1) * 8) * 2;

    for (int ch = 0; ch < GK_TOT / GBK; ch++) {
        #pragma unroll
        for (int i = 0; i < 2; i++) {
            int u = t + i * 256;
            int r = u >> 2;
            int c = (u & 3) * 8;
            uint32_t so = (uint32_t)(r * SROW + c) * 2;
            size_t ga = (size_t)(m0 + r) * GK_TOT + ch * GBK + c;
            *(uint4*)(smem + (sAhi - sb) + so) = *(const uint4*)(Ahi + ga);
            *(uint4*)(smem + (sAlo - sb) + so) = *(const uint4*)(Alo + ga);
            size_t gb = (size_t)(n0 + r) * GK_TOT + ch * GBK + c;
            *(uint4*)(smem + (sBhi - sb) + so) = *(const uint4*)(Bhi + gb);
            *(uint4*)(smem + (sBlo - sb) + so) = *(const uint4*)(Blo + gb);
        }
        __syncthreads();

        #pragma unroll
        for (int ks = 0; ks < 2; ks++) {
            const uint32_t kb = ks * 16 * 2;
            uint32_t ah[4][4], al[4][4], bh[2][4], bl[2][4];
            #pragma unroll
            for (int mt = 0; mt < 4; mt++) {
                uint32_t ra = (uint32_t)((wm0 + mt * 16) * SROW) * 2 + aoff + kb;
                ldm_x4(sAhi + ra, ah[mt][0], ah[mt][1], ah[mt][2], ah[mt][3]);
                ldm_x4(sAlo + ra, al[mt][0], al[mt][1], al[mt][2], al[mt][3]);
            }
            #pragma unroll
            for (int np = 0; np < 2; np++) {
                uint32_t rb = (uint32_t)((wn0 + np * 16) * SROW) * 2 + boff + kb;
                ldm_x4(sBhi + rb, bh[np][0], bh[np][1], bh[np][2], bh[np][3]);
                ldm_x4(sBlo + rb, bl[np][0], bl[np][1], bl[np][2], bl[np][3]);
            }
            #pragma unroll
            for (int mt = 0; mt < 4; mt++)
                #pragma unroll
                for (int nt = 0; nt < 4; nt++) {
                    uint32_t h0 = bh[nt >> 1][(nt & 1) * 2];
                    uint32_t h1 = bh[nt >> 1][(nt & 1) * 2 + 1];
                    uint32_t l0 = bl[nt >> 1][(nt & 1) * 2];
                    uint32_t l1 = bl[nt >> 1][(nt & 1) * 2 + 1];
                    mma_bf16(acc[mt][nt], ah[mt], h0, h1);
                    mma_bf16(acc[mt][nt], ah[mt], l0, l1);
                    mma_bf16(acc[mt][nt], al[mt], h0, h1);
                }
        }
        __syncthreads();
    }

    const int g  = lane >> 2;
    const int cq = (lane & 3) * 2;
    #pragma unroll
    for (int mt = 0; mt < 4; mt++)
        #pragma unroll
        for (int nt = 0; nt < 4; nt++) {
            float* cp = C + (size_t)(m0 + wm0 + mt * 16 + g) * N
                          + n0 + wn0 + nt * 8 + cq;
            *(float2*)cp = make_float2(acc[mt][nt][0], acc[mt][nt][1]);
            *(float2*)(cp + (size_t)8 * N) = make_float2(acc[mt][nt][2], acc[mt][nt][3]);
        }
}

// ============================================================================
// Flash attention with mma.sync (bf16 hi/lo split), online softmax, poly-exp.
// BM=128 (8 warps x 16 rows), BN=64 keys/iter, D=64.
// S = Qhi*Khi + Qhi*Klo + Qlo*Khi;  O += Phi*Vhi + Phi*Vlo + Plo*Vhi.
// P A-fragments come straight from the S accumulator layout (no smem trip).
// ============================================================================
#define SRA 72   // halves per smem row (144 B) for all attn tiles

__global__ __launch_bounds__(256) void attn_mma_kernel(
    const float* __restrict__ qkv, float* __restrict__ y)
{
    extern __shared__ char smem[];
    const uint32_t sb = smem_u32(smem);
    const uint32_t QHI = 0,               QLO = 128 * SRA * 2;        // 18432 each
    const uint32_t KHI = 2 * 128 * SRA * 2;                            // 36864
    const uint32_t KLO = KHI + 64 * SRA * 2;                           // +9216
    const uint32_t VHI = KLO + 64 * SRA * 2;
    const uint32_t VLO = VHI + 64 * SRA * 2;                           // total 73728

    const int t    = threadIdx.x;
    const int w    = t >> 5;
    const int lane = t & 31;
    const int qt   = gridDim.x - 1 - blockIdx.x;   // heavy tiles first
    const int bh   = blockIdx.y;
    const int b    = bh >> 3;
    const int h    = bh & 7;
    const float scale = 0.125f;

    const size_t base = (size_t)b * T_SEQ * (3 * C_EMB);
    const float* Qg = qkv + base + (size_t)qt * 128 * (3 * C_EMB) + h * HD;
    const float* Kg = qkv + base + C_EMB + h * HD;
    const float* Vg = qkv + base + 2 * C_EMB + h * HD;

    // ---- load Q tile (128 x 64), pre-scaled, bf16 hi/lo split ----
    #pragma unroll
    for (int i = 0; i < 8; i++) {
        int u  = t + i * 256;             // 0..2047
        int r  = u >> 4;                  // 0..127
        int c4 = (u & 15) * 4;            // 0..60
        float4 v = *(const float4*)(Qg + (size_t)r * (3 * C_EMB) + c4);
        uint32_t h0, l0, h1, l1;
        split2(v.x * scale, v.y * scale, h0, l0);
        split2(v.z * scale, v.w * scale, h1, l1);
        uint32_t so = (uint32_t)(r * SRA + c4) * 2;
        *(uint2*)(smem + QHI + so) = make_uint2(h0, h1);
        *(uint2*)(smem + QLO + so) = make_uint2(l0, l1);
    }

    // fragment lane addressing
    const uint32_t aoff = ((uint32_t)(lane & 15) * SRA + (lane >> 4) * 8) * 2;
    const uint32_t boff = ((uint32_t)(((lane >> 4) & 1) * 8 + (lane & 7)) * SRA
                          + ((lane >> 3) & 1) * 8) * 2;
    const uint32_t voff = ((uint32_t)(((lane >> 3) & 1) * 8 + (lane & 7)) * SRA
                          + (lane >> 4) * 8) * 2;   // trans ldmatrix on V[key][d]

    const int g = lane >> 2;
    const int cq = (lane & 3) * 2;
    const int row0 = qt * 128 + w * 16 + g;          // this lane's row (and +8)

    float m0 = -1e30f, m1 = -1e30f, l0 = 0.f, l1 = 0.f;
    float o[8][4];
    #pragma unroll
    for (int i = 0; i < 8; i++)
        #pragma unroll
        for (int j = 0; j < 4; j++) o[i][j] = 0.f;

    const int jt_max = 2 * qt + 1;
    for (int jt = 0; jt <= jt_max; jt++) {
        __syncthreads();   // smem reuse guard (also covers Q fill on jt==0)
        // ---- load K, V tiles (64 x 64) as bf16 hi/lo ----
        #pragma unroll
        for (int i = 0; i < 4; i++) {
            int u  = t + i * 256;
            int r  = u >> 4;              // 0..63
            int c4 = (u & 15) * 4;
            const size_t grow = (size_t)(jt * 64 + r) * (3 * C_EMB);
            uint32_t so = (uint32_t)(r * SRA + c4) * 2;
            float4 kv = *(const float4*)(Kg + grow + c4);
            uint32_t h0, lo0, h1, lo1;
            split2(kv.x, kv.y, h0, lo0);
            split2(kv.z, kv.w, h1, lo1);
            *(uint2*)(smem + KHI + so) = make_uint2(h0, h1);
            *(uint2*)(smem + KLO + so) = make_uint2(lo0, lo1);
            float4 vv = *(const float4*)(Vg + grow + c4);
            split2(vv.x, vv.y, h0, lo0);
            split2(vv.z, vv.w, h1, lo1);
            *(uint2*)(smem + VHI + so) = make_uint2(h0, h1);
            *(uint2*)(smem + VLO + so) = make_uint2(lo0, lo1);
        }
        __syncthreads();

        // ---- S = Q @ K^T  (warp: 16 rows x 64 keys) ----
        float s[8][4];
        #pragma unroll
        for (int i = 0; i < 8; i++)
            #pragma unroll
            for (int j = 0; j < 4; j++) s[i][j] = 0.f;

        #pragma unroll
        for (int kt = 0; kt < 4; kt++) {
            uint32_t qh[4], ql[4];
            uint32_t ra = (uint32_t)(w * 16 * SRA + kt * 16) * 2 + aoff;
            ldm_x4(sb + QHI + ra, qh[0], qh[1], qh[2], qh[3]);
            ldm_x4(sb + QLO + ra, ql[0], ql[1], ql[2], ql[3]);
            uint32_t kh[4][4], kl[4][4];
            #pragma unroll
            for (int np = 0; np < 4; np++) {
                uint32_t rb = (uint32_t)(np * 16 * SRA + kt * 16) * 2 + boff;
                ldm_x4(sb + KHI + rb, kh[np][0], kh[np][1], kh[np][2], kh[np][3]);
                ldm_x4(sb + KLO + rb, kl[np][0], kl[np][1], kl[np][2], kl[np][3]);
            }
            #pragma unroll
            for (int nt = 0; nt < 8; nt++) {
                uint32_t h0 = kh[nt >> 1][(nt & 1) * 2];
                uint32_t h1 = kh[nt >> 1][(nt & 1) * 2 + 1];
                uint32_t lo0 = kl[nt >> 1][(nt & 1) * 2];
                uint32_t lo1 = kl[nt >> 1][(nt & 1) * 2 + 1];
                mma_bf16(s[nt], qh, h0, h1);
                mma_bf16(s[nt], qh, lo0, lo1);
                mma_bf16(s[nt], ql, h0, h1);
            }
        }

        // ---- causal mask (straddling tiles only) ----
        if (jt >= 2 * qt) {
            #pragma unroll
            for (int nt = 0; nt < 8; nt++) {
                int col = jt * 64 + nt * 8 + cq;
                if (col     > row0)     s[nt][0] = -1e30f;
                if (col + 1 > row0)     s[nt][1] = -1e30f;
                if (col     > row0 + 8) s[nt][2] = -1e30f;
                if (col + 1 > row0 + 8) s[nt][3] = -1e30f;
            }
        }

        // ---- online softmax (rows g and g+8; quad shuffle reduce) ----
        float mx0 = -1e30f, mx1 = -1e30f;
        #pragma unroll
        for (int nt = 0; nt < 8; nt++) {
            mx0 = fmaxf(mx0, fmaxf(s[nt][0], s[nt][1]));
            mx1 = fmaxf(mx1, fmaxf(s[nt][2], s[nt][3]));
        }
        mx0 = fmaxf(mx0, __shfl_xor_sync(0xffffffffu, mx0, 1));
        mx0 = fmaxf(mx0, __shfl_xor_sync(0xffffffffu, mx0, 2));
        mx1 = fmaxf(mx1, __shfl_xor_sync(0xffffffffu, mx1, 1));
        mx1 = fmaxf(mx1, __shfl_xor_sync(0xffffffffu, mx1, 2));
        float mn0 = fmaxf(m0, mx0), mn1 = fmaxf(m1, mx1);
        float a0 = fexp(m0 - mn0), a1 = fexp(m1 - mn1);
        m0 = mn0; m1 = mn1;
        float rs0 = 0.f, rs1 = 0.f;
        #pragma unroll
        for (int nt = 0; nt < 8; nt++) {
            s[nt][0] = fexp(s[nt][0] - mn0);
            s[nt][1] = fexp(s[nt][1] - mn0);
            s[nt][2] = fexp(s[nt][2] - mn1);
            s[nt][3] = fexp(s[nt][3] - mn1);
            rs0 += s[nt][0] + s[nt][1];
            rs1 += s[nt][2] + s[nt][3];
        }
        rs0 += __shfl_xor_sync(0xffffffffu, rs0, 1);
        rs0 += __shfl_xor_sync(0xffffffffu, rs0, 2);
        rs1 += __shfl_xor_sync(0xffffffffu, rs1, 1);
        rs1 += __shfl_xor_sync(0xffffffffu, rs1, 2);
        l0 = l0 * a0 + rs0;
        l1 = l1 * a1 + rs1;
        #pragma unroll
        for (int dt = 0; dt < 8; dt++) {
            o[dt][0] *= a0; o[dt][1] *= a0;
            o[dt][2] *= a1; o[dt][3] *= a1;
        }

        // ---- O += P @ V (P frags direct from accumulators) ----
        #pragma unroll
        for (int kt = 0; kt < 4; kt++) {
            uint32_t ph[4], pl[4];
            split2(s[2 * kt][0],     s[2 * kt][1],     ph[0], pl[0]);
            split2(s[2 * kt][2],     s[2 * kt][3],     ph[1], pl[1]);
            split2(s[2 * kt + 1][0], s[2 * kt + 1][1], ph[2], pl[2]);
            split2(s[2 * kt + 1][2], s[2 * kt + 1][3], ph[3], pl[3]);
            uint32_t vh[4][4], vl[4][4];
            #pragma unroll
            for (int dn = 0; dn < 4; dn++) {
                uint32_t rv = (uint32_t)(kt * 16 * SRA + dn * 16) * 2 + voff;
                ldm_x4t(sb + VHI + rv, vh[dn][0], vh[dn][1], vh[dn][2], vh[dn][3]);
                ldm_x4t(sb + VLO + rv, vl[dn][0], vl[dn][1], vl[dn][2], vl[dn][3]);
            }
            #pragma unroll
            for (int dt = 0; dt < 8; dt++) {
                uint32_t h0 = vh[dt >> 1][(dt & 1) * 2];
                uint32_t h1 = vh[dt >> 1][(dt & 1) * 2 + 1];
                uint32_t lo0 = vl[dt >> 1][(dt & 1) * 2];
                uint32_t lo1 = vl[dt >> 1][(dt & 1) * 2 + 1];
                mma_bf16(o[dt], ph, h0, h1);
                mma_bf16(o[dt], ph, lo0, lo1);
                mma_bf16(o[dt], pl, h0, h1);
            }
        }
    }

    // ---- epilogue: normalize, store y[b, row, h*64 + d] ----
    const float inv0 = 1.f / l0, inv1 = 1.f / l1;
    float* yg = y + ((size_t)b * T_SEQ + row0) * C_EMB + h * HD;
    #pragma unroll
    for (int dt = 0; dt < 8; dt++) {
        float* cp = yg + dt * 8 + cq;
        *(float2*)cp = make_float2(o[dt][0] * inv0, o[dt][1] * inv0);
        *(float2*)(cp + (size_t)8 * C_EMB) = make_float2(o[dt][2] * inv1, o[dt][3] * inv1);
    }
}

// ============================================================================
extern "C" void kernel_launch(void* const* d_in, const int* in_sizes, int n_in,
                              void* d_out, int out_size)
{
    const float* x      = (const float*)d_in[0];   // [B,T,C]
    const float* W_attn = (const float*)d_in[1];   // [C, 3C]
    const float* W_proj = (const float*)d_in[2];   // [C, C]
    float* out = (float*)d_out;                    // [B,T,C]

    float *qkv_ptr, *y_ptr;
    __nv_bfloat16 *xhi, *xlo, *wahi, *walo, *wphi, *wplo;
    cudaGetSymbolAddress((void**)&qkv_ptr, g_qkv);
    cudaGetSymbolAddress((void**)&y_ptr,  g_y);
    cudaGetSymbolAddress((void**)&xhi, g_xhi);
    cudaGetSymbolAddress((void**)&xlo, g_xlo);
    cudaGetSymbolAddress((void**)&wahi, g_wa_hi);
    cudaGetSymbolAddress((void**)&walo, g_wa_lo);
    cudaGetSymbolAddress((void**)&wphi, g_wp_hi);
    cudaGetSymbolAddress((void**)&wplo, g_wp_lo);

    const int smem_attn = (2 * 128 + 4 * 64) * SRA * 2;   // 73,728 B
    const int smem_gemm = 4 * 128 * SROW * 2;             // 40,960 B
    static int attr_set = 0;
    if (!attr_set) {
        cudaFuncSetAttribute(attn_mma_kernel,
                             cudaFuncAttributeMaxDynamicSharedMemorySize, smem_attn);
        cudaFuncSetAttribute(mma_gemm,
                             cudaFuncAttributeMaxDynamicSharedMemorySize, smem_gemm);
        attr_set = 1;
    }

    // Prep: weights transposed+split (K-major), x split
    convert_wT<<<dim3(3 * C_EMB / 32, C_EMB / 32), 256>>>(W_attn, wahi, walo, C_EMB, 3 * C_EMB);
    convert_wT<<<dim3(C_EMB / 32, C_EMB / 32), 256>>>(W_proj, wphi, wplo, C_EMB, C_EMB);
    convert_split<<<(BT * C_EMB / 4 + 255) / 256, 256>>>(x, xhi, xlo, BT * C_EMB / 4);

    // 1) qkv = x @ W_attn  (mma.sync bf16 split)
    mma_gemm<<<dim3(3 * C_EMB / 128, BT / 128), 256, smem_gemm>>>(
        xhi, xlo, wahi, walo, qkv_ptr, BT, 3 * C_EMB);

    // 2) causal attention (mma.sync)
    attn_mma_kernel<<<dim3(T_SEQ / 128, NB * NH), 256, smem_attn>>>(qkv_ptr, y_ptr);

    // 3) out = y @ W_proj  (mma.sync); reuse xhi/xlo for y split
    convert_split<<<(BT * C_EMB / 4 + 255) / 256, 256>>>(y_ptr, xhi, xlo, BT * C_EMB / 4);
    mma_gemm<<<dim3(C_EMB / 128, BT / 128), 256, smem_gemm>>>(
        xhi, xlo, wphi, wplo, out, BT, C_EMB);
}

// round 9
// speedup vs baseline: 2.8633x; 1.0175x over previous
#include <cuda_runtime.h>
#include <cuda_bf16.h>
#include <cstdint>
#include <math.h>

// Problem constants
#define T_SEQ 4096
#define NB    2
#define C_EMB 512
#define NH    8
#define HD    64
#define BT    (NB * T_SEQ)   // 8192

// Scratch (static device globals; no allocation allowed)
__device__ float g_qkv[(size_t)BT * 3 * C_EMB];              // [8192, 1536]
__device__ float g_y[(size_t)BT * C_EMB];                    // [8192, 512]
__device__ __nv_bfloat16 g_xhi[(size_t)BT * C_EMB];          // x or y hi  [8192,512]
__device__ __nv_bfloat16 g_xlo[(size_t)BT * C_EMB];          // x or y lo
__device__ __nv_bfloat16 g_wa_hi[(size_t)3 * C_EMB * C_EMB]; // W_attn^T hi [1536,512]
__device__ __nv_bfloat16 g_wa_lo[(size_t)3 * C_EMB * C_EMB];
__device__ __nv_bfloat16 g_wp_hi[(size_t)C_EMB * C_EMB];     // W_proj^T hi [512,512]
__device__ __nv_bfloat16 g_wp_lo[(size_t)C_EMB * C_EMB];
// Head-major pre-split Q (scaled) / K / V: [b][h][t][d]
__device__ __nv_bfloat16 g_qhi[(size_t)BT * C_EMB];
__device__ __nv_bfloat16 g_qlo[(size_t)BT * C_EMB];
__device__ __nv_bfloat16 g_khi[(size_t)BT * C_EMB];
__device__ __nv_bfloat16 g_klo[(size_t)BT * C_EMB];
__device__ __nv_bfloat16 g_vhi[(size_t)BT * C_EMB];
__device__ __nv_bfloat16 g_vlo[(size_t)BT * C_EMB];

// ============================================================================
// PTX helpers (sm_80-era features only — plain sm_103 target safe)
// ============================================================================
__device__ __forceinline__ uint32_t smem_u32(const void* p) {
    uint32_t a;
    asm("{ .reg .u64 t; cvta.to.shared.u64 t, %1; cvt.u32.u64 %0, t; }"
        : "=r"(a) : "l"(p));
    return a;
}
__device__ __forceinline__ void ldm_x4(uint32_t addr, uint32_t& r0, uint32_t& r1,
                                       uint32_t& r2, uint32_t& r3) {
    asm volatile("ldmatrix.sync.aligned.m8n8.x4.shared.b16 {%0,%1,%2,%3}, [%4];"
                 : "=r"(r0), "=r"(r1), "=r"(r2), "=r"(r3) : "r"(addr));
}
__device__ __forceinline__ void ldm_x4t(uint32_t addr, uint32_t& r0, uint32_t& r1,
                                        uint32_t& r2, uint32_t& r3) {
    asm volatile("ldmatrix.sync.aligned.m8n8.x4.trans.shared.b16 {%0,%1,%2,%3}, [%4];"
                 : "=r"(r0), "=r"(r1), "=r"(r2), "=r"(r3) : "r"(addr));
}
__device__ __forceinline__ void mma_bf16(float* d, const uint32_t* a,
                                         uint32_t b0, uint32_t b1) {
    asm volatile(
        "mma.sync.aligned.m16n8k16.row.col.f32.bf16.bf16.f32 "
        "{%0,%1,%2,%3}, {%4,%5,%6,%7}, {%8,%9}, {%0,%1,%2,%3};"
        : "+f"(d[0]), "+f"(d[1]), "+f"(d[2]), "+f"(d[3])
        : "r"(a[0]), "r"(a[1]), "r"(a[2]), "r"(a[3]), "r"(b0), "r"(b1));
}
__device__ __forceinline__ uint32_t pack_bf16(float a, float b) {
    uint32_t r;
    asm("cvt.rn.bf16x2.f32 %0, %1, %2;" : "=r"(r) : "f"(b), "f"(a));
    return r;
}
__device__ __forceinline__ void split2(float x, float y, uint32_t& h, uint32_t& l) {
    h = pack_bf16(x, y);
    float xh = __uint_as_float((h & 0xFFFFu) << 16);
    float yh = __uint_as_float(h & 0xFFFF0000u);
    l = pack_bf16(x - xh, y - yh);
}
#define CP16(dst, src) \
    asm volatile("cp.async.cg.shared.global [%0], [%1], 16;" \
                 :: "r"(dst), "l"(src) : "memory")
#define CP_COMMIT() asm volatile("cp.async.commit_group;" ::: "memory")
#define CP_WAIT1()  asm volatile("cp.async.wait_group 1;" ::: "memory")
#define CP_WAIT0()  asm volatile("cp.async.wait_group 0;" ::: "memory")

// ============================================================================
// Fast exp on fma/alu pipes (no MUFU). Valid for x <= 0; ~2e-6 rel err.
// ============================================================================
__device__ __forceinline__ float fexp(float x) {
    float y = fmaxf(x * 1.44269504088896341f, -126.0f);
    float t = y + 12582912.0f;
    int   n = __float_as_int(t) - 0x4B400000;
    float f = y - (t - 12582912.0f);
    float p = fmaf(f, 0.0013333558f, 0.0096181291f);
    p = fmaf(f, p, 0.0555041087f);
    p = fmaf(f, p, 0.2402264791f);
    p = fmaf(f, p, 0.6931472028f);
    p = fmaf(f, p, 1.0f);
    return __int_as_float(__float_as_int(p) + (n << 23));
}

// ============================================================================
// Prep kernels
// ============================================================================
__global__ __launch_bounds__(256) void convert_split(
    const float* __restrict__ src, __nv_bfloat16* __restrict__ hi,
    __nv_bfloat16* __restrict__ lo, int n4)
{
    int i = blockIdx.x * 256 + threadIdx.x;
    if (i >= n4) return;
    float4 v = ((const float4*)src)[i];
    uint32_t h0, l0, h1, l1;
    split2(v.x, v.y, h0, l0);
    split2(v.z, v.w, h1, l1);
    ((uint2*)hi)[i] = make_uint2(h0, h1);
    ((uint2*)lo)[i] = make_uint2(l0, l1);
}

// W [K,N] row-major -> Wt hi/lo [N,K] (K-major) bf16 split. grid (N/32, K/32).
__global__ __launch_bounds__(256) void convert_wT(
    const float* __restrict__ W, __nv_bfloat16* __restrict__ Thi,
    __nv_bfloat16* __restrict__ Tlo, int K, int N)
{
    __shared__ float tile[32][33];
    const int bx = blockIdx.x * 32, by = blockIdx.y * 32;
    const int tx = threadIdx.x & 31, ty = threadIdx.x >> 5;
    #pragma unroll
    for (int i = 0; i < 4; i++) {
        int r = ty + i * 8;
        tile[r][tx] = W[(size_t)(by + r) * N + bx + tx];
    }
    __syncthreads();
    #pragma unroll
    for (int i = 0; i < 4; i++) {
        int r = ty + i * 8;
        float v = tile[tx][r];
        __nv_bfloat16 h = __float2bfloat16(v);
        __nv_bfloat16 l = __float2bfloat16(v - __bfloat162float(h));
        size_t o = (size_t)(bx + r) * K + by + tx;
        Thi[o] = h; Tlo[o] = l;
    }
}

// g_qkv [bt][1536] -> head-major bf16 hi/lo Q(scaled)/K/V: [b][h][t][64]
__global__ __launch_bounds__(256) void convert_qkv(
    const float* __restrict__ qkv,
    __nv_bfloat16* __restrict__ qhi, __nv_bfloat16* __restrict__ qlo,
    __nv_bfloat16* __restrict__ khi, __nv_bfloat16* __restrict__ klo,
    __nv_bfloat16* __restrict__ vhi, __nv_bfloat16* __restrict__ vlo)
{
    int idx = blockIdx.x * 256 + threadIdx.x;          // over BT*512/4
    int bt = idx >> 7;
    int cc = (idx & 127) * 4;
    int b  = bt >> 12, tt = bt & (T_SEQ - 1);
    int h  = cc >> 6,  d  = cc & 63;
    size_t src = (size_t)bt * (3 * C_EMB);
    size_t dst = ((((size_t)(b * NH + h)) * T_SEQ + tt) * HD + d) >> 2;  // uint2 units

    float4 q = *(const float4*)(qkv + src + cc);
    uint32_t h0, l0, h1, l1;
    split2(q.x * 0.125f, q.y * 0.125f, h0, l0);
    split2(q.z * 0.125f, q.w * 0.125f, h1, l1);
    ((uint2*)qhi)[dst] = make_uint2(h0, h1);
    ((uint2*)qlo)[dst] = make_uint2(l0, l1);

    float4 k = *(const float4*)(qkv + src + C_EMB + cc);
    split2(k.x, k.y, h0, l0);
    split2(k.z, k.w, h1, l1);
    ((uint2*)khi)[dst] = make_uint2(h0, h1);
    ((uint2*)klo)[dst] = make_uint2(l0, l1);

    float4 v = *(const float4*)(qkv + src + 2 * C_EMB + cc);
    split2(v.x, v.y, h0, l0);
    split2(v.z, v.w, h1, l1);
    ((uint2*)vhi)[dst] = make_uint2(h0, h1);
    ((uint2*)vlo)[dst] = make_uint2(l0, l1);
}

// ============================================================================
// mma.sync bf16-split GEMM with cp.async double buffering.
// C[M,N] = A[M,512] @ B[N,512]^T, 3-term hi/lo split.
// ============================================================================
#define GK_TOT 512
#define GBK    32
#define SROW   40                    // halves per smem row (80 B)
#define GTILE  (128 * SROW * 2)      // 10240 B per tile
#define GSTAGE (4 * GTILE)           // 40960 B per stage

__global__ __launch_bounds__(256) void mma_gemm(
    const __nv_bfloat16* __restrict__ Ahi, const __nv_bfloat16* __restrict__ Alo,
    const __nv_bfloat16* __restrict__ Bhi, const __nv_bfloat16* __restrict__ Blo,
    float* __restrict__ C, int M, int N)
{
    extern __shared__ char smem[];
    const uint32_t sb = smem_u32(smem);

    const int t    = threadIdx.x;
    const int wid  = t >> 5;
    const int lane = t & 31;
    const int m0   = blockIdx.y * 128;
    const int n0   = blockIdx.x * 128;
    const int wm0  = (wid & 1) * 64;
    const int wn0  = (wid >> 1) * 32;

    float acc[4][4][4];
    #pragma unroll
    for (int i = 0; i < 4; i++)
        #pragma unroll
        for (int j = 0; j < 4; j++)
            #pragma unroll
            for (int k = 0; k < 4; k++) acc[i][j][k] = 0.f;

    const uint32_t aoff = ((uint32_t)(lane & 15) * SROW + (lane >> 4) * 8) * 2;
    const uint32_t boff = ((uint32_t)(((lane >> 4) & 1) * 8 + (lane & 7)) * SROW
                          + ((lane >> 3) & 1) * 8) * 2;

    // prefetch lambda: stage ch into buffer s
    auto prefetch = [&](int ch, int s) {
        #pragma unroll
        for (int i = 0; i < 8; i++) {
            int u   = t + i * 256;            // 0..2047
            int arr = u >> 9;                 // 0..3 : Ahi,Alo,Bhi,Blo
            int rem = u & 511;
            int r   = rem >> 2;               // 0..127
            int c8  = (rem & 3) * 8;          // halves
            uint32_t dst = sb + s * GSTAGE + arr * GTILE
                         + (uint32_t)(r * SROW + c8) * 2;
            const __nv_bfloat16* gp =
                (arr == 0) ? Ahi + (size_t)(m0 + r) * GK_TOT :
                (arr == 1) ? Alo + (size_t)(m0 + r) * GK_TOT :
                (arr == 2) ? Bhi + (size_t)(n0 + r) * GK_TOT :
                             Blo + (size_t)(n0 + r) * GK_TOT;
            CP16(dst, gp + ch * GBK + c8);
        }
    };

    prefetch(0, 0);
    CP_COMMIT();

    for (int ch = 0; ch < GK_TOT / GBK; ch++) {
        const int cs = ch & 1;
        if (ch < GK_TOT / GBK - 1) {
            prefetch(ch + 1, cs ^ 1);
            CP_COMMIT();
            CP_WAIT1();
        } else {
            CP_WAIT0();
        }
        __syncthreads();

        const uint32_t sAhi = sb + cs * GSTAGE;
        const uint32_t sAlo = sAhi + GTILE;
        const uint32_t sBhi = sAhi + 2 * GTILE;
        const uint32_t sBlo = sAhi + 3 * GTILE;

        #pragma unroll
        for (int ks = 0; ks < 2; ks++) {
            const uint32_t kb = ks * 16 * 2;
            uint32_t ah[4][4], al[4][4], bh[2][4], bl[2][4];
            #pragma unroll
            for (int mt = 0; mt < 4; mt++) {
                uint32_t ra = (uint32_t)((wm0 + mt * 16) * SROW) * 2 + aoff + kb;
                ldm_x4(sAhi + ra, ah[mt][0], ah[mt][1], ah[mt][2], ah[mt][3]);
                ldm_x4(sAlo + ra, al[mt][0], al[mt][1], al[mt][2], al[mt][3]);
            }
            #pragma unroll
            for (int np = 0; np < 2; np++) {
                uint32_t rb = (uint32_t)((wn0 + np * 16) * SROW) * 2 + boff + kb;
                ldm_x4(sBhi + rb, bh[np][0], bh[np][1], bh[np][2], bh[np][3]);
                ldm_x4(sBlo + rb, bl[np][0], bl[np][1], bl[np][2], bl[np][3]);
            }
            #pragma unroll
            for (int mt = 0; mt < 4; mt++)
                #pragma unroll
                for (int nt = 0; nt < 4; nt++) {
                    uint32_t h0 = bh[nt >> 1][(nt & 1) * 2];
                    uint32_t h1 = bh[nt >> 1][(nt & 1) * 2 + 1];
                    uint32_t l0 = bl[nt >> 1][(nt & 1) * 2];
                    uint32_t l1 = bl[nt >> 1][(nt & 1) * 2 + 1];
                    mma_bf16(acc[mt][nt], ah[mt], h0, h1);
                    mma_bf16(acc[mt][nt], ah[mt], l0, l1);
                    mma_bf16(acc[mt][nt], al[mt], h0, h1);
                }
        }
        __syncthreads();
    }

    const int g  = lane >> 2;
    const int cq = (lane & 3) * 2;
    #pragma unroll
    for (int mt = 0; mt < 4; mt++)
        #pragma unroll
        for (int nt = 0; nt < 4; nt++) {
            float* cp = C + (size_t)(m0 + wm0 + mt * 16 + g) * N
                          + n0 + wn0 + nt * 8 + cq;
            *(float2*)cp = make_float2(acc[mt][nt][0], acc[mt][nt][1]);
            *(float2*)(cp + (size_t)8 * N) = make_float2(acc[mt][nt][2], acc[mt][nt][3]);
        }
}

// ============================================================================
// Flash attention: mma.sync + pre-split head-major bf16 Q/K/V + cp.async
// double-buffered K/V. BM=128 (8 warps x 16 rows), BN=64, D=64.
// Q fragments hoisted to registers; Q smem area reused as pipeline stage 1.
// ============================================================================
#define SRA    72                    // halves per smem row (144 B)
#define ATILE  (64 * SRA * 2)        // 9216 B per K/V array tile
#define ASTAGE (4 * ATILE)           // 36864 B per stage (khi,klo,vhi,vlo)

__global__ __launch_bounds__(256) void attn_mma_kernel(
    const __nv_bfloat16* __restrict__ qhi, const __nv_bfloat16* __restrict__ qlo,
    const __nv_bfloat16* __restrict__ khi, const __nv_bfloat16* __restrict__ klo,
    const __nv_bfloat16* __restrict__ vhi, const __nv_bfloat16* __restrict__ vlo,
    float* __restrict__ y)
{
    extern __shared__ char smem[];
    const uint32_t sb = smem_u32(smem);

    const int t    = threadIdx.x;
    const int w    = t >> 5;
    const int lane = t & 31;
    const int qt   = gridDim.x - 1 - blockIdx.x;   // heavy tiles first
    const int bh   = blockIdx.y;
    const int b    = bh >> 3;
    const int h    = bh & 7;

    const size_t hb = ((size_t)(b * NH + h)) << 18;   // head base (4096*64)
    const __nv_bfloat16* Kh = khi + hb;
    const __nv_bfloat16* Kl = klo + hb;
    const __nv_bfloat16* Vh = vhi + hb;
    const __nv_bfloat16* Vl = vlo + hb;

    auto prefetch = [&](int jt, int s) {
        #pragma unroll
        for (int i = 0; i < 8; i++) {
            int u   = t + i * 256;              // 0..2047
            int arr = u >> 9;                   // 0..3
            int rem = u & 511;
            int r   = rem >> 3;                 // 0..63
            int c8  = (rem & 7) * 8;
            uint32_t dst = sb + s * ASTAGE + arr * ATILE
                         + (uint32_t)(r * SRA + c8) * 2;
            const __nv_bfloat16* gp = (arr == 0) ? Kh : (arr == 1) ? Kl
                                    : (arr == 2) ? Vh : Vl;
            CP16(dst, gp + ((size_t)(jt * 64 + r) << 6) + c8);
        }
    };

    // prefetch key tile 0 into stage 0 (overlaps with Q staging)
    prefetch(0, 0);
    CP_COMMIT();

    // ---- stage Q tile (128 x 64 hi/lo) into stage-1 area, extract frags ----
    {
        const __nv_bfloat16* Qh = qhi + hb + ((size_t)qt * 128 << 6);
        const __nv_bfloat16* Ql = qlo + hb + ((size_t)qt * 128 << 6);
        #pragma unroll
        for (int i = 0; i < 8; i++) {
            int u   = t + i * 256;              // 0..2047
            int arr = u >> 10;                  // 0: hi, 1: lo
            int rem = u & 1023;
            int r   = rem >> 3;                 // 0..127
            int c8  = (rem & 7) * 8;
            const __nv_bfloat16* gp = arr ? Ql : Qh;
            *(uint4*)(smem + ASTAGE + arr * (128 * SRA * 2)
                      + (uint32_t)(r * SRA + c8) * 2) =
                *(const uint4*)(gp + (r << 6) + c8);
        }
    }
    __syncthreads();

    const uint32_t aoff = ((uint32_t)(lane & 15) * SRA + (lane >> 4) * 8) * 2;
    const uint32_t boff = ((uint32_t)(((lane >> 4) & 1) * 8 + (lane & 7)) * SRA
                          + ((lane >> 3) & 1) * 8) * 2;
    const uint32_t voff = ((uint32_t)(((lane >> 3) & 1) * 8 + (lane & 7)) * SRA
                          + (lane >> 4) * 8) * 2;

    uint32_t qh[4][4], ql[4][4];
    {
        const uint32_t QHI = sb + ASTAGE, QLO = QHI + 128 * SRA * 2;
        #pragma unroll
        for (int kt = 0; kt < 4; kt++) {
            uint32_t ra = (uint32_t)(w * 16 * SRA + kt * 16) * 2 + aoff;
            ldm_x4(QHI + ra, qh[kt][0], qh[kt][1], qh[kt][2], qh[kt][3]);
            ldm_x4(QLO + ra, ql[kt][0], ql[kt][1], ql[kt][2], ql[kt][3]);
        }
    }
    __syncthreads();   // all warps done with Q area -> stage 1 reusable

    const int g   = lane >> 2;
    const int cq  = (lane & 3) * 2;
    const int row0 = qt * 128 + w * 16 + g;

    float m0 = -1e30f, m1 = -1e30f, l0 = 0.f, l1 = 0.f;
    float o[8][4];
    #pragma unroll
    for (int i = 0; i < 8; i++)
        #pragma unroll
        for (int j = 0; j < 4; j++) o[i][j] = 0.f;

    const int jt_max = 2 * qt + 1;
    for (int jt = 0; jt <= jt_max; jt++) {
        const int cs = jt & 1;
        if (jt < jt_max) {
            prefetch(jt + 1, cs ^ 1);
            CP_COMMIT();
            CP_WAIT1();
        } else {
            CP_WAIT0();
        }
        __syncthreads();

        const uint32_t SKH = sb + cs * ASTAGE;
        const uint32_t SKL = SKH + ATILE;
        const uint32_t SVH = SKH + 2 * ATILE;
        const uint32_t SVL = SKH + 3 * ATILE;

        // ---- S = Q @ K^T ----
        float s[8][4];
        #pragma unroll
        for (int i = 0; i < 8; i++)
            #pragma unroll
            for (int j = 0; j < 4; j++) s[i][j] = 0.f;

        #pragma unroll
        for (int kt = 0; kt < 4; kt++) {
            #pragma unroll
            for (int np = 0; np < 4; np++) {
                uint32_t kh4[4], kl4[4];
                uint32_t rb = (uint32_t)(np * 16 * SRA + kt * 16) * 2 + boff;
                ldm_x4(SKH + rb, kh4[0], kh4[1], kh4[2], kh4[3]);
                ldm_x4(SKL + rb, kl4[0], kl4[1], kl4[2], kl4[3]);
                #pragma unroll
                for (int qn = 0; qn < 2; qn++) {
                    int nt = np * 2 + qn;
                    mma_bf16(s[nt], qh[kt], kh4[qn * 2], kh4[qn * 2 + 1]);
                    mma_bf16(s[nt], qh[kt], kl4[qn * 2], kl4[qn * 2 + 1]);
                    mma_bf16(s[nt], ql[kt], kh4[qn * 2], kh4[qn * 2 + 1]);
                }
            }
        }

        // ---- causal mask (straddling tiles only) ----
        if (jt >= 2 * qt) {
            #pragma unroll
            for (int nt = 0; nt < 8; nt++) {
                int col = jt * 64 + nt * 8 + cq;
                if (col     > row0)     s[nt][0] = -1e30f;
                if (col + 1 > row0)     s[nt][1] = -1e30f;
                if (col     > row0 + 8) s[nt][2] = -1e30f;
                if (col + 1 > row0 + 8) s[nt][3] = -1e30f;
            }
        }

        // ---- online softmax ----
        float mx0 = -1e30f, mx1 = -1e30f;
        #pragma unroll
        for (int nt = 0; nt < 8; nt++) {
            mx0 = fmaxf(mx0, fmaxf(s[nt][0], s[nt][1]));
            mx1 = fmaxf(mx1, fmaxf(s[nt][2], s[nt][3]));
        }
        mx0 = fmaxf(mx0, __shfl_xor_sync(0xffffffffu, mx0, 1));
        mx0 = fmaxf(mx0, __shfl_xor_sync(0xffffffffu, mx0, 2));
        mx1 = fmaxf(mx1, __shfl_xor_sync(0xffffffffu, mx1, 1));
        mx1 = fmaxf(mx1, __shfl_xor_sync(0xffffffffu, mx1, 2));
        float mn0 = fmaxf(m0, mx0), mn1 = fmaxf(m1, mx1);
        float a0 = fexp(m0 - mn0), a1 = fexp(m1 - mn1);
        m0 = mn0; m1 = mn1;
        float rs0 = 0.f, rs1 = 0.f;
        #pragma unroll
        for (int nt = 0; nt < 8; nt++) {
            s[nt][0] = fexp(s[nt][0] - mn0);
            s[nt][1] = fexp(s[nt][1] - mn0);
            s[nt][2] = fexp(s[nt][2] - mn1);
            s[nt][3] = fexp(s[nt][3] - mn1);
            rs0 += s[nt][0] + s[nt][1];
            rs1 += s[nt][2] + s[nt][3];
        }
        rs0 += __shfl_xor_sync(0xffffffffu, rs0, 1);
        rs0 += __shfl_xor_sync(0xffffffffu, rs0, 2);
        rs1 += __shfl_xor_sync(0xffffffffu, rs1, 1);
        rs1 += __shfl_xor_sync(0xffffffffu, rs1, 2);
        l0 = l0 * a0 + rs0;
        l1 = l1 * a1 + rs1;
        #pragma unroll
        for (int dt = 0; dt < 8; dt++) {
            o[dt][0] *= a0; o[dt][1] *= a0;
            o[dt][2] *= a1; o[dt][3] *= a1;
        }

        // ---- O += P @ V ----
        #pragma unroll
        for (int kt = 0; kt < 4; kt++) {
            uint32_t ph[4], pl[4];
            split2(s[2 * kt][0],     s[2 * kt][1],     ph[0], pl[0]);
            split2(s[2 * kt][2],     s[2 * kt][3],     ph[1], pl[1]);
            split2(s[2 * kt + 1][0], s[2 * kt + 1][1], ph[2], pl[2]);
            split2(s[2 * kt + 1][2], s[2 * kt + 1][3], ph[3], pl[3]);
            #pragma unroll
            for (int dn = 0; dn < 4; dn++) {
                uint32_t vh4[4], vl4[4];
                uint32_t rv = (uint32_t)(kt * 16 * SRA + dn * 16) * 2 + voff;
                ldm_x4t(SVH + rv, vh4[0], vh4[1], vh4[2], vh4[3]);
                ldm_x4t(SVL + rv, vl4[0], vl4[1], vl4[2], vl4[3]);
                #pragma unroll
                for (int qn = 0; qn < 2; qn++) {
                    int dt = dn * 2 + qn;
                    mma_bf16(o[dt], ph, vh4[qn * 2], vh4[qn * 2 + 1]);
                    mma_bf16(o[dt], ph, vl4[qn * 2], vl4[qn * 2 + 1]);
                    mma_bf16(o[dt], pl, vh4[qn * 2], vh4[qn * 2 + 1]);
                }
            }
        }
        __syncthreads();
    }

    // ---- epilogue ----
    const float inv0 = 1.f / l0, inv1 = 1.f / l1;
    float* yg = y + ((size_t)b * T_SEQ + row0) * C_EMB + h * HD;
    #pragma unroll
    for (int dt = 0; dt < 8; dt++) {
        float* cp = yg + dt * 8 + cq;
        *(float2*)cp = make_float2(o[dt][0] * inv0, o[dt][1] * inv0);
        *(float2*)(cp + (size_t)8 * C_EMB) = make_float2(o[dt][2] * inv1, o[dt][3] * inv1);
    }
}

// ============================================================================
extern "C" void kernel_launch(void* const* d_in, const int* in_sizes, int n_in,
                              void* d_out, int out_size)
{
    const float* x      = (const float*)d_in[0];
    const float* W_attn = (const float*)d_in[1];
    const float* W_proj = (const float*)d_in[2];
    float* out = (float*)d_out;

    float *qkv_ptr, *y_ptr;
    __nv_bfloat16 *xhi, *xlo, *wahi, *walo, *wphi, *wplo;
    __nv_bfloat16 *qhi, *qlo, *khi, *klo, *vhi, *vlo;
    cudaGetSymbolAddress((void**)&qkv_ptr, g_qkv);
    cudaGetSymbolAddress((void**)&y_ptr,  g_y);
    cudaGetSymbolAddress((void**)&xhi, g_xhi);
    cudaGetSymbolAddress((void**)&xlo, g_xlo);
    cudaGetSymbolAddress((void**)&wahi, g_wa_hi);
    cudaGetSymbolAddress((void**)&walo, g_wa_lo);
    cudaGetSymbolAddress((void**)&wphi, g_wp_hi);
    cudaGetSymbolAddress((void**)&wplo, g_wp_lo);
    cudaGetSymbolAddress((void**)&qhi, g_qhi);
    cudaGetSymbolAddress((void**)&qlo, g_qlo);
    cudaGetSymbolAddress((void**)&khi, g_khi);
    cudaGetSymbolAddress((void**)&klo, g_klo);
    cudaGetSymbolAddress((void**)&vhi, g_vhi);
    cudaGetSymbolAddress((void**)&vlo, g_vlo);

    const int smem_attn = 2 * ASTAGE;    // 73,728 B
    const int smem_gemm = 2 * GSTAGE;    // 81,920 B
    static int attr_set = 0;
    if (!attr_set) {
        cudaFuncSetAttribute(attn_mma_kernel,
                             cudaFuncAttributeMaxDynamicSharedMemorySize, smem_attn);
        cudaFuncSetAttribute(mma_gemm,
                             cudaFuncAttributeMaxDynamicSharedMemorySize, smem_gemm);
        attr_set = 1;
    }

    // Prep: weights transposed+split (K-major), x split
    convert_wT<<<dim3(3 * C_EMB / 32, C_EMB / 32), 256>>>(W_attn, wahi, walo, C_EMB, 3 * C_EMB);
    convert_wT<<<dim3(C_EMB / 32, C_EMB / 32), 256>>>(W_proj, wphi, wplo, C_EMB, C_EMB);
    convert_split<<<(BT * C_EMB / 4 + 255) / 256, 256>>>(x, xhi, xlo, BT * C_EMB / 4);

    // 1) qkv = x @ W_attn
    mma_gemm<<<dim3(3 * C_EMB / 128, BT / 128), 256, smem_gemm>>>(
        xhi, xlo, wahi, walo, qkv_ptr, BT, 3 * C_EMB);

    // 1b) split qkv into head-major bf16 hi/lo (Q pre-scaled)
    convert_qkv<<<BT * C_EMB / 4 / 256, 256>>>(qkv_ptr, qhi, qlo, khi, klo, vhi, vlo);

    // 2) causal attention (mma.sync, double-buffered)
    attn_mma_kernel<<<dim3(T_SEQ / 128, NB * NH), 256, smem_attn>>>(
        qhi, qlo, khi, klo, vhi, vlo, y_ptr);

    // 3) out = y @ W_proj
    convert_split<<<(BT * C_EMB / 4 + 255) / 256, 256>>>(y_ptr, xhi, xlo, BT * C_EMB / 4);
    mma_gemm<<<dim3(C_EMB / 128, BT / 128), 256, smem_gemm>>>(
        xhi, xlo, wphi, wplo, out, BT, C_EMB);
}